// round 1
// baseline (speedup 1.0000x reference)
#include <cuda_runtime.h>
#include <math.h>

#define TT 4
#define NN 50000
#define DD 256
#define HH 8
#define RR 4
#define EE 200000
#define DK 32
#define D4 1024

// ---------------- scratch (device globals: no allocation allowed) ----------------
__device__ float    g_Q[TT * NN * DD];
__device__ float    g_K[TT * NN * DD];
__device__ float    g_V[TT * NN * DD];
__device__ float    g_agg[TT * NN * DD];
__device__ float    g_h[TT * NN * DD];
__device__ float    g_f[(size_t)TT * NN * D4];   // 819 MB FFN intermediate
__device__ float    g_vrel[EE * DD];             // per-relation V_rel (reused; also reused as FFN2 out)
__device__ float    g_f2[TT * NN * DD];          // FFN2 output
__device__ float    g_logits[EE * HH];
__device__ float    g_p[EE * HH];
__device__ unsigned g_m[NN * HH];                // encoded segment max
__device__ float    g_z[NN * HH];                // segment sum

// monotonic float <-> uint encoding for atomicMax
__device__ __forceinline__ unsigned fenc(float f) {
    unsigned u = __float_as_uint(f);
    return (u & 0x80000000u) ? ~u : (u | 0x80000000u);
}
__device__ __forceinline__ float fdec(unsigned u) {
    unsigned b = (u & 0x80000000u) ? (u & 0x7FFFFFFFu) : ~u;
    return __uint_as_float(b);
}

// ---------------- tiled SGEMM with bias (+optional exact gelu) ----------------
// C[M,N] = A[M,K] @ B[K,N] + bias[N]; batched over blockIdx.z with strides.
// BM=BN=128, BK=16, 256 threads, 8x8 per thread. N % 128 == 0, K % 16 == 0 required.
__global__ void __launch_bounds__(256)
sgemm_bias_act(const float* __restrict__ A, const float* __restrict__ B,
               const float* __restrict__ bias, float* __restrict__ C,
               int M, int K, int N,
               long long sA, long long sB, long long sBias, long long sC,
               int gelu_act)
{
    const int t = blockIdx.z;
    A    += (long long)t * sA;
    B    += (long long)t * sB;
    bias += (long long)t * sBias;
    C    += (long long)t * sC;

    const int bm = blockIdx.x * 128;
    const int bn = blockIdx.y * 128;

    __shared__ float As[16][128];
    __shared__ float Bs[16][128];

    const int tid = threadIdx.x;
    const int tr = tid >> 4;   // 0..15
    const int tc = tid & 15;   // 0..15

    float acc[8][8];
#pragma unroll
    for (int i = 0; i < 8; i++)
#pragma unroll
        for (int j = 0; j < 8; j++) acc[i][j] = 0.f;

    for (int k0 = 0; k0 < K; k0 += 16) {
        // load A tile (128 rows x 16 cols) as float4, store transposed
#pragma unroll
        for (int it = 0; it < 2; it++) {
            int idx = tid + it * 256;        // 0..511
            int row = idx >> 2;
            int c4  = (idx & 3) * 4;
            int gr  = bm + row;
            float4 v = make_float4(0.f, 0.f, 0.f, 0.f);
            if (gr < M) v = *(const float4*)&A[(long long)gr * K + k0 + c4];
            As[c4 + 0][row] = v.x;
            As[c4 + 1][row] = v.y;
            As[c4 + 2][row] = v.z;
            As[c4 + 3][row] = v.w;
        }
        // load B tile (16 rows x 128 cols)
#pragma unroll
        for (int it = 0; it < 2; it++) {
            int idx = tid + it * 256;
            int row = idx >> 5;
            int c4  = (idx & 31) * 4;
            float4 v = *(const float4*)&B[(long long)(k0 + row) * N + bn + c4];
            *(float4*)&Bs[row][c4] = v;
        }
        __syncthreads();

#pragma unroll
        for (int kk = 0; kk < 16; kk++) {
            float4 a0 = *(const float4*)&As[kk][tr * 8];
            float4 a1 = *(const float4*)&As[kk][tr * 8 + 4];
            float4 b0 = *(const float4*)&Bs[kk][tc * 8];
            float4 b1 = *(const float4*)&Bs[kk][tc * 8 + 4];
            float ar[8] = {a0.x, a0.y, a0.z, a0.w, a1.x, a1.y, a1.z, a1.w};
            float br[8] = {b0.x, b0.y, b0.z, b0.w, b1.x, b1.y, b1.z, b1.w};
#pragma unroll
            for (int i = 0; i < 8; i++)
#pragma unroll
                for (int j = 0; j < 8; j++)
                    acc[i][j] = fmaf(ar[i], br[j], acc[i][j]);
        }
        __syncthreads();
    }

    // epilogue
#pragma unroll
    for (int i = 0; i < 8; i++) {
        int gr = bm + tr * 8 + i;
        if (gr >= M) continue;
#pragma unroll
        for (int j = 0; j < 8; j += 4) {
            int gc = bn + tc * 8 + j;
            float4 v;
            v.x = acc[i][j + 0] + bias[gc + 0];
            v.y = acc[i][j + 1] + bias[gc + 1];
            v.z = acc[i][j + 2] + bias[gc + 2];
            v.w = acc[i][j + 3] + bias[gc + 3];
            if (gelu_act) {
                v.x = 0.5f * v.x * (1.f + erff(v.x * 0.7071067811865476f));
                v.y = 0.5f * v.y * (1.f + erff(v.y * 0.7071067811865476f));
                v.z = 0.5f * v.z * (1.f + erff(v.z * 0.7071067811865476f));
                v.w = 0.5f * v.w * (1.f + erff(v.w * 0.7071067811865476f));
            }
            *(float4*)&C[(long long)gr * N + gc] = v;
        }
    }
}

// ---------------- edge phase: logits + V_rel ----------------
// grid.y = head; warp per edge; lane = f index within head.
__global__ void __launch_bounds__(256)
edge_logits_kernel(const float* __restrict__ Qbase, const float* __restrict__ Kbase,
                   const float* __restrict__ Vbase,
                   const int* __restrict__ esrc, const int* __restrict__ edst,
                   const float* __restrict__ Wa, const float* __restrict__ Wm,
                   const float* __restrict__ rel_bias, int r)
{
    __shared__ float sWa[DK * DK];
    __shared__ float sWm[DK * DK];
    const int h = blockIdx.y;
    for (int i = threadIdx.x; i < DK * DK; i += 256) {
        sWa[i] = Wa[h * DK * DK + i];
        sWm[i] = Wm[h * DK * DK + i];
    }
    __syncthreads();

    const float brel = rel_bias[r];
    const int warp = threadIdx.x >> 5;
    const int lane = threadIdx.x & 31;

    for (int e = blockIdx.x * 8 + warp; e < EE; e += gridDim.x * 8) {
        int s = esrc[e];
        int d = edst[e];
        float kv = Kbase[(long long)s * DD + h * DK + lane];
        float vv = Vbase[(long long)s * DD + h * DK + lane];
        float qv = Qbase[(long long)d * DD + h * DK + lane];
        float krel = 0.f, vrel = 0.f;
#pragma unroll
        for (int d0 = 0; d0 < DK; d0++) {
            float kb = __shfl_sync(0xffffffffu, kv, d0);
            float vb = __shfl_sync(0xffffffffu, vv, d0);
            krel = fmaf(kb, sWa[d0 * DK + lane], krel);
            vrel = fmaf(vb, sWm[d0 * DK + lane], vrel);
        }
        float lg = qv * krel;
#pragma unroll
        for (int o = 16; o > 0; o >>= 1) lg += __shfl_xor_sync(0xffffffffu, lg, o);
        if (lane == 0)
            g_logits[e * HH + h] = lg * 0.17677669529663687f + brel;
        g_vrel[(long long)e * DD + h * DK + lane] = vrel;
    }
}

__global__ void seg_max_kernel(const int* __restrict__ edst)
{
    int i = blockIdx.x * blockDim.x + threadIdx.x;
    if (i >= EE * HH) return;
    int e = i >> 3;           // /HH
    int h = i & 7;
    int d = edst[e];
    atomicMax(&g_m[d * HH + h], fenc(g_logits[i]));
}

__global__ void seg_exp_kernel(const int* __restrict__ edst)
{
    int i = blockIdx.x * blockDim.x + threadIdx.x;
    if (i >= EE * HH) return;
    int e = i >> 3;
    int h = i & 7;
    int d = edst[e];
    float m = fdec(g_m[d * HH + h]);
    float p = expf(g_logits[i] - m);
    g_p[i] = p;
    atomicAdd(&g_z[d * HH + h], p);
}

__global__ void seg_msg_kernel(const int* __restrict__ edst, float* __restrict__ aggbase)
{
    long long i = (long long)blockIdx.x * 256 + threadIdx.x;   // over EE*DD
    if (i >= (long long)EE * DD) return;
    int e = (int)(i >> 8);
    int c = (int)(i & 255);
    int h = c >> 5;
    int d = edst[e];
    float attn = g_p[e * HH + h] / g_z[d * HH + h];
    atomicAdd(&aggbase[(long long)d * DD + c], attn * g_vrel[i]);
}

// ---------------- layernorm(residual) ----------------
// warp per row of 256 elems
__global__ void __launch_bounds__(256)
ln_kernel(const float* __restrict__ X, const float* __restrict__ Res,
          const float* __restrict__ G, const float* __restrict__ B,
          float* __restrict__ Out)
{
    int row = blockIdx.x * 8 + (threadIdx.x >> 5);
    if (row >= TT * NN) return;
    int lane = threadIdx.x & 31;
    int t = row / NN;
    const float* xr = X + (long long)row * DD;
    const float* rr = Res + (long long)row * DD;
    float v[8];
    float sum = 0.f;
#pragma unroll
    for (int j = 0; j < 8; j++) {
        v[j] = xr[lane + 32 * j] + rr[lane + 32 * j];
        sum += v[j];
    }
#pragma unroll
    for (int o = 16; o > 0; o >>= 1) sum += __shfl_xor_sync(0xffffffffu, sum, o);
    float mu = sum * (1.f / 256.f);
    float var = 0.f;
#pragma unroll
    for (int j = 0; j < 8; j++) {
        float dlt = v[j] - mu;
        var = fmaf(dlt, dlt, var);
    }
#pragma unroll
    for (int o = 16; o > 0; o >>= 1) var += __shfl_xor_sync(0xffffffffu, var, o);
    float rstd = rsqrtf(var * (1.f / 256.f) + 1e-5f);
#pragma unroll
    for (int j = 0; j < 8; j++) {
        int c = lane + 32 * j;
        Out[(long long)row * DD + c] = (v[j] - mu) * rstd * G[t * DD + c] + B[t * DD + c];
    }
}

// ---------------- launch ----------------
extern "C" void kernel_launch(void* const* d_in, const int* in_sizes, int n_in,
                              void* d_out, int out_size)
{
    const float* x       = (const float*)d_in[0];
    const int*   esrc    = (const int*)d_in[1];
    const int*   edst    = (const int*)d_in[2];
    const float* Wq      = (const float*)d_in[3];
    const float* bq      = (const float*)d_in[4];
    const float* Wk      = (const float*)d_in[5];
    const float* bk      = (const float*)d_in[6];
    const float* Wv      = (const float*)d_in[7];
    const float* bv      = (const float*)d_in[8];
    const float* W_attn  = (const float*)d_in[9];
    const float* W_msg   = (const float*)d_in[10];
    const float* relbias = (const float*)d_in[11];
    const float* ln1_g   = (const float*)d_in[12];
    const float* ln1_b   = (const float*)d_in[13];
    const float* ln2_g   = (const float*)d_in[14];
    const float* ln2_b   = (const float*)d_in[15];
    const float* ffn_w1  = (const float*)d_in[16];
    const float* ffn_b1  = (const float*)d_in[17];
    const float* ffn_w2  = (const float*)d_in[18];
    const float* ffn_b2  = (const float*)d_in[19];
    float* out = (float*)d_out;

    float *pQ, *pK, *pV, *pagg, *ph, *pf, *pf2, *pz;
    unsigned* pm;
    cudaGetSymbolAddress((void**)&pQ, g_Q);
    cudaGetSymbolAddress((void**)&pK, g_K);
    cudaGetSymbolAddress((void**)&pV, g_V);
    cudaGetSymbolAddress((void**)&pagg, g_agg);
    cudaGetSymbolAddress((void**)&ph, g_h);
    cudaGetSymbolAddress((void**)&pf, g_f);
    cudaGetSymbolAddress((void**)&pf2, g_f2);
    cudaGetSymbolAddress((void**)&pm, g_m);
    cudaGetSymbolAddress((void**)&pz, g_z);

    const long long sND = (long long)NN * DD;
    const long long sDD = (long long)DD * DD;

    // QKV projections, batched over the 4 node types
    dim3 gqkv((NN + 127) / 128, DD / 128, TT);
    sgemm_bias_act<<<gqkv, 256>>>(x, Wq, bq, pQ, NN, DD, DD, sND, sDD, DD, sND, 0);
    sgemm_bias_act<<<gqkv, 256>>>(x, Wk, bk, pK, NN, DD, DD, sND, sDD, DD, sND, 0);
    sgemm_bias_act<<<gqkv, 256>>>(x, Wv, bv, pV, NN, DD, DD, sND, sDD, DD, sND, 0);

    cudaMemsetAsync(pagg, 0, sizeof(float) * TT * NN * DD, 0);

    const int stype[RR] = {1, 2, 3, 1};
    const int dtype[RR] = {0, 0, 3, 3};
    for (int r = 0; r < RR; r++) {
        cudaMemsetAsync(pm, 0, sizeof(unsigned) * NN * HH, 0);
        cudaMemsetAsync(pz, 0, sizeof(float) * NN * HH, 0);
        dim3 ga(2048, HH);
        edge_logits_kernel<<<ga, 256>>>(
            pQ + (long long)dtype[r] * sND,
            pK + (long long)stype[r] * sND,
            pV + (long long)stype[r] * sND,
            esrc + r * EE, edst + r * EE,
            W_attn + r * HH * DK * DK, W_msg + r * HH * DK * DK,
            relbias, r);
        int ehThreads = EE * HH;
        seg_max_kernel<<<(ehThreads + 255) / 256, 256>>>(edst + r * EE);
        seg_exp_kernel<<<(ehThreads + 255) / 256, 256>>>(edst + r * EE);
        long long edThreads = (long long)EE * DD;
        seg_msg_kernel<<<(unsigned)((edThreads + 255) / 256), 256>>>(
            edst + r * EE, pagg + (long long)dtype[r] * sND);
    }

    // h = LN1(x + agg)
    ln_kernel<<<(TT * NN + 7) / 8, 256>>>(x, pagg, ln1_g, ln1_b, ph);

    // FFN: f = gelu(h @ W1 + b1); f2 = f @ W2 + b2
    dim3 gf1((NN + 127) / 128, D4 / 128, TT);
    sgemm_bias_act<<<gf1, 256>>>(ph, ffn_w1, ffn_b1, pf, NN, DD, D4,
                                 sND, (long long)DD * D4, D4, (long long)NN * D4, 1);
    dim3 gf2((NN + 127) / 128, DD / 128, TT);
    sgemm_bias_act<<<gf2, 256>>>(pf, ffn_w2, ffn_b2, pf2, NN, D4, DD,
                                 (long long)NN * D4, (long long)D4 * DD, DD, sND, 0);

    // out = LN2(h + f2)
    ln_kernel<<<(TT * NN + 7) / 8, 256>>>(ph, pf2, ln2_g, ln2_b, out);

    (void)in_sizes; (void)n_in; (void)out_size;
}

// round 2
// speedup vs baseline: 1.4282x; 1.4282x over previous
#include <cuda_runtime.h>
#include <math.h>

#define TT 4
#define NN 50000
#define DD 256
#define HH 8
#define RR 4
#define EE 200000
#define DK 32
#define D4 1024

// ---------------- scratch (device globals: no allocation allowed) ----------------
__device__ float    g_Q[TT * NN * DD];        // Q projections (only dst types 0,3 filled)
__device__ float    g_krel[NN * DD];          // per-relation node-level K_rel (reused)
__device__ float    g_vreln[NN * DD];         // per-relation node-level V_rel (reused)
__device__ float    g_agg[TT * NN * DD];
__device__ float    g_h[TT * NN * DD];
__device__ float    g_f[(size_t)TT * NN * D4];
__device__ float    g_f2[TT * NN * DD];
__device__ float    g_logits[EE * HH];
__device__ float    g_p[EE * HH];
__device__ unsigned g_m[NN * HH];
__device__ float    g_z[NN * HH];
__device__ float    g_Wkr[RR * DD * DD];      // folded Wk @ BD(W_attn)
__device__ float    g_Wvr[RR * DD * DD];      // folded Wv @ BD(W_msg)
__device__ float    g_bkr[RR * DD];
__device__ float    g_bvr[RR * DD];

// monotonic float <-> uint encoding for atomicMax
__device__ __forceinline__ unsigned fenc(float f) {
    unsigned u = __float_as_uint(f);
    return (u & 0x80000000u) ? ~u : (u | 0x80000000u);
}
__device__ __forceinline__ float fdec(unsigned u) {
    unsigned b = (u & 0x80000000u) ? (u & 0x7FFFFFFFu) : ~u;
    return __uint_as_float(b);
}

// ---------------- tiled SGEMM with bias (+optional exact gelu) ----------------
__global__ void __launch_bounds__(256)
sgemm_bias_act(const float* __restrict__ A, const float* __restrict__ B,
               const float* __restrict__ bias, float* __restrict__ C,
               int M, int K, int N,
               long long sA, long long sB, long long sBias, long long sC,
               int gelu_act)
{
    const int t = blockIdx.z;
    A    += (long long)t * sA;
    B    += (long long)t * sB;
    bias += (long long)t * sBias;
    C    += (long long)t * sC;

    const int bm = blockIdx.x * 128;
    const int bn = blockIdx.y * 128;

    __shared__ float As[16][128];
    __shared__ float Bs[16][128];

    const int tid = threadIdx.x;
    const int tr = tid >> 4;
    const int tc = tid & 15;

    float acc[8][8];
#pragma unroll
    for (int i = 0; i < 8; i++)
#pragma unroll
        for (int j = 0; j < 8; j++) acc[i][j] = 0.f;

    for (int k0 = 0; k0 < K; k0 += 16) {
#pragma unroll
        for (int it = 0; it < 2; it++) {
            int idx = tid + it * 256;
            int row = idx >> 2;
            int c4  = (idx & 3) * 4;
            int gr  = bm + row;
            float4 v = make_float4(0.f, 0.f, 0.f, 0.f);
            if (gr < M) v = *(const float4*)&A[(long long)gr * K + k0 + c4];
            As[c4 + 0][row] = v.x;
            As[c4 + 1][row] = v.y;
            As[c4 + 2][row] = v.z;
            As[c4 + 3][row] = v.w;
        }
#pragma unroll
        for (int it = 0; it < 2; it++) {
            int idx = tid + it * 256;
            int row = idx >> 5;
            int c4  = (idx & 31) * 4;
            float4 v = *(const float4*)&B[(long long)(k0 + row) * N + bn + c4];
            *(float4*)&Bs[row][c4] = v;
        }
        __syncthreads();

#pragma unroll
        for (int kk = 0; kk < 16; kk++) {
            float4 a0 = *(const float4*)&As[kk][tr * 8];
            float4 a1 = *(const float4*)&As[kk][tr * 8 + 4];
            float4 b0 = *(const float4*)&Bs[kk][tc * 8];
            float4 b1 = *(const float4*)&Bs[kk][tc * 8 + 4];
            float ar[8] = {a0.x, a0.y, a0.z, a0.w, a1.x, a1.y, a1.z, a1.w};
            float br[8] = {b0.x, b0.y, b0.z, b0.w, b1.x, b1.y, b1.z, b1.w};
#pragma unroll
            for (int i = 0; i < 8; i++)
#pragma unroll
                for (int j = 0; j < 8; j++)
                    acc[i][j] = fmaf(ar[i], br[j], acc[i][j]);
        }
        __syncthreads();
    }

#pragma unroll
    for (int i = 0; i < 8; i++) {
        int gr = bm + tr * 8 + i;
        if (gr >= M) continue;
#pragma unroll
        for (int j = 0; j < 8; j += 4) {
            int gc = bn + tc * 8 + j;
            float4 v;
            v.x = acc[i][j + 0] + bias[gc + 0];
            v.y = acc[i][j + 1] + bias[gc + 1];
            v.z = acc[i][j + 2] + bias[gc + 2];
            v.w = acc[i][j + 3] + bias[gc + 3];
            if (gelu_act) {
                v.x = 0.5f * v.x * (1.f + erff(v.x * 0.7071067811865476f));
                v.y = 0.5f * v.y * (1.f + erff(v.y * 0.7071067811865476f));
                v.z = 0.5f * v.z * (1.f + erff(v.z * 0.7071067811865476f));
                v.w = 0.5f * v.w * (1.f + erff(v.w * 0.7071067811865476f));
            }
            *(float4*)&C[(long long)gr * N + gc] = v;
        }
    }
}

// ---------------- fold relation matrices into projection weights ----------------
// outW[d, h*32+f] = sum_k W[st, d, h*32+k] * Wrel[r, h, k, f]
__global__ void __launch_bounds__(256)
combine_w_kernel(const float* __restrict__ W, const float* __restrict__ Wrel,
                 float* __restrict__ outW, int st, int r)
{
    int idx = blockIdx.x * 256 + threadIdx.x;
    if (idx >= DD * DD) return;
    int d = idx >> 8;
    int c = idx & 255;
    int h = c >> 5, f = c & 31;
    const float* wrow = W + ((long long)st * DD + d) * DD + h * DK;
    const float* wr   = Wrel + ((long long)(r * HH + h) * DK) * DK + f;
    float s = 0.f;
#pragma unroll
    for (int k = 0; k < DK; k++) s = fmaf(wrow[k], wr[k * DK], s);
    outW[idx] = s;
}

__global__ void
combine_b_kernel(const float* __restrict__ b, const float* __restrict__ Wrel,
                 float* __restrict__ outb, int st, int r)
{
    int c = blockIdx.x * blockDim.x + threadIdx.x;
    if (c >= DD) return;
    int h = c >> 5, f = c & 31;
    const float* br = b + st * DD + h * DK;
    const float* wr = Wrel + ((long long)(r * HH + h) * DK) * DK + f;
    float s = 0.f;
#pragma unroll
    for (int k = 0; k < DK; k++) s = fmaf(br[k], wr[k * DK], s);
    outb[c] = s;
}

// ---------------- edge logits: pure gather + dot over all heads ----------------
// warp per edge; lane = h*4 + q; each lane dots 8 floats of head h.
__global__ void __launch_bounds__(256)
edge_dot_kernel(const float* __restrict__ Qbase, const float* __restrict__ Krel,
                const int* __restrict__ esrc, const int* __restrict__ edst,
                const float* __restrict__ rel_bias, int r)
{
    const int warp = threadIdx.x >> 5;
    const int lane = threadIdx.x & 31;
    const int h = lane >> 2, q = lane & 3;
    const float brel = rel_bias[r];
    int e = blockIdx.x * 8 + warp;
    if (e >= EE) return;
    int s = esrc[e];
    int d = edst[e];
    const float4* qp = (const float4*)&Qbase[(long long)d * DD + h * DK + q * 8];
    const float4* kp = (const float4*)&Krel[(long long)s * DD + h * DK + q * 8];
    float4 q0 = qp[0], q1 = qp[1];
    float4 k0 = kp[0], k1 = kp[1];
    float acc = q0.x * k0.x + q0.y * k0.y + q0.z * k0.z + q0.w * k0.w
              + q1.x * k1.x + q1.y * k1.y + q1.z * k1.z + q1.w * k1.w;
    acc += __shfl_xor_sync(0xffffffffu, acc, 1);
    acc += __shfl_xor_sync(0xffffffffu, acc, 2);
    if (q == 0)
        g_logits[e * HH + h] = acc * 0.17677669529663687f + brel;
}

__global__ void seg_max_kernel(const int* __restrict__ edst)
{
    int i = blockIdx.x * blockDim.x + threadIdx.x;
    if (i >= EE * HH) return;
    int e = i >> 3;
    int h = i & 7;
    int d = edst[e];
    atomicMax(&g_m[d * HH + h], fenc(g_logits[i]));
}

__global__ void seg_exp_kernel(const int* __restrict__ edst)
{
    int i = blockIdx.x * blockDim.x + threadIdx.x;
    if (i >= EE * HH) return;
    int e = i >> 3;
    int h = i & 7;
    int d = edst[e];
    float m = fdec(g_m[d * HH + h]);
    float p = expf(g_logits[i] - m);
    g_p[i] = p;
    atomicAdd(&g_z[d * HH + h], p);
}

// scatter messages: attn * Vrel[src] -> agg[dst], vectorized red.v4
__global__ void __launch_bounds__(256)
seg_msg_kernel(const int* __restrict__ esrc, const int* __restrict__ edst,
               const float* __restrict__ Vrel, float* __restrict__ aggbase)
{
    long long i = (long long)blockIdx.x * 256 + threadIdx.x;  // over EE*64
    if (i >= (long long)EE * 64) return;
    int e = (int)(i >> 6);
    int w = (int)(i & 63);
    int c = w * 4;
    int h = c >> 5;
    int s = esrc[e];
    int d = edst[e];
    float attn = g_p[e * HH + h] / g_z[d * HH + h];
    float4 v = *(const float4*)&Vrel[(long long)s * DD + c];
    float* dst = &aggbase[(long long)d * DD + c];
    asm volatile("red.global.add.v4.f32 [%0], {%1,%2,%3,%4};"
                 :: "l"(dst), "f"(attn * v.x), "f"(attn * v.y),
                    "f"(attn * v.z), "f"(attn * v.w)
                 : "memory");
}

// ---------------- layernorm(residual) ----------------
__global__ void __launch_bounds__(256)
ln_kernel(const float* __restrict__ X, const float* __restrict__ Res,
          const float* __restrict__ G, const float* __restrict__ B,
          float* __restrict__ Out)
{
    int row = blockIdx.x * 8 + (threadIdx.x >> 5);
    if (row >= TT * NN) return;
    int lane = threadIdx.x & 31;
    int t = row / NN;
    const float* xr = X + (long long)row * DD;
    const float* rr = Res + (long long)row * DD;
    float v[8];
    float sum = 0.f;
#pragma unroll
    for (int j = 0; j < 8; j++) {
        v[j] = xr[lane + 32 * j] + rr[lane + 32 * j];
        sum += v[j];
    }
#pragma unroll
    for (int o = 16; o > 0; o >>= 1) sum += __shfl_xor_sync(0xffffffffu, sum, o);
    float mu = sum * (1.f / 256.f);
    float var = 0.f;
#pragma unroll
    for (int j = 0; j < 8; j++) {
        float dlt = v[j] - mu;
        var = fmaf(dlt, dlt, var);
    }
#pragma unroll
    for (int o = 16; o > 0; o >>= 1) var += __shfl_xor_sync(0xffffffffu, var, o);
    float rstd = rsqrtf(var * (1.f / 256.f) + 1e-5f);
#pragma unroll
    for (int j = 0; j < 8; j++) {
        int c = lane + 32 * j;
        Out[(long long)row * DD + c] = (v[j] - mu) * rstd * G[t * DD + c] + B[t * DD + c];
    }
}

// ---------------- launch ----------------
extern "C" void kernel_launch(void* const* d_in, const int* in_sizes, int n_in,
                              void* d_out, int out_size)
{
    const float* x       = (const float*)d_in[0];
    const int*   esrc    = (const int*)d_in[1];
    const int*   edst    = (const int*)d_in[2];
    const float* Wq      = (const float*)d_in[3];
    const float* bq      = (const float*)d_in[4];
    const float* Wk      = (const float*)d_in[5];
    const float* bk      = (const float*)d_in[6];
    const float* Wv      = (const float*)d_in[7];
    const float* bv      = (const float*)d_in[8];
    const float* W_attn  = (const float*)d_in[9];
    const float* W_msg   = (const float*)d_in[10];
    const float* relbias = (const float*)d_in[11];
    const float* ln1_g   = (const float*)d_in[12];
    const float* ln1_b   = (const float*)d_in[13];
    const float* ln2_g   = (const float*)d_in[14];
    const float* ln2_b   = (const float*)d_in[15];
    const float* ffn_w1  = (const float*)d_in[16];
    const float* ffn_b1  = (const float*)d_in[17];
    const float* ffn_w2  = (const float*)d_in[18];
    const float* ffn_b2  = (const float*)d_in[19];
    float* out = (float*)d_out;

    float *pQ, *pkrel, *pvreln, *pagg, *ph, *pf, *pf2, *pz;
    float *pWkr, *pWvr, *pbkr, *pbvr;
    unsigned* pm;
    cudaGetSymbolAddress((void**)&pQ, g_Q);
    cudaGetSymbolAddress((void**)&pkrel, g_krel);
    cudaGetSymbolAddress((void**)&pvreln, g_vreln);
    cudaGetSymbolAddress((void**)&pagg, g_agg);
    cudaGetSymbolAddress((void**)&ph, g_h);
    cudaGetSymbolAddress((void**)&pf, g_f);
    cudaGetSymbolAddress((void**)&pf2, g_f2);
    cudaGetSymbolAddress((void**)&pm, g_m);
    cudaGetSymbolAddress((void**)&pz, g_z);
    cudaGetSymbolAddress((void**)&pWkr, g_Wkr);
    cudaGetSymbolAddress((void**)&pWvr, g_Wvr);
    cudaGetSymbolAddress((void**)&pbkr, g_bkr);
    cudaGetSymbolAddress((void**)&pbvr, g_bvr);

    const long long sND = (long long)NN * DD;
    const long long sDD = (long long)DD * DD;

    const int stype[RR] = {1, 2, 3, 1};
    const int dtype[RR] = {0, 0, 3, 3};

    // ---- fold relation matrices into K/V projection weights ----
    for (int r = 0; r < RR; r++) {
        combine_w_kernel<<<(DD * DD + 255) / 256, 256>>>(Wk, W_attn, pWkr + (long long)r * sDD, stype[r], r);
        combine_w_kernel<<<(DD * DD + 255) / 256, 256>>>(Wv, W_msg, pWvr + (long long)r * sDD, stype[r], r);
        combine_b_kernel<<<1, DD>>>(bk, W_attn, pbkr + r * DD, stype[r], r);
        combine_b_kernel<<<1, DD>>>(bv, W_msg, pbvr + r * DD, stype[r], r);
    }

    // ---- Q projections (only dst types 0 and 3 are used) ----
    dim3 gq((NN + 127) / 128, DD / 128, 1);
    sgemm_bias_act<<<gq, 256>>>(x + 0 * sND, Wq + 0 * sDD, bq + 0 * DD, pQ + 0 * sND,
                                NN, DD, DD, 0, 0, 0, 0, 0);
    sgemm_bias_act<<<gq, 256>>>(x + 3 * sND, Wq + 3 * sDD, bq + 3 * DD, pQ + 3 * sND,
                                NN, DD, DD, 0, 0, 0, 0, 0);

    cudaMemsetAsync(pagg, 0, sizeof(float) * TT * NN * DD, 0);

    for (int r = 0; r < RR; r++) {
        const int st = stype[r], dt = dtype[r];
        // node-level K_rel / V_rel via folded-weight GEMMs
        sgemm_bias_act<<<gq, 256>>>(x + (long long)st * sND, pWkr + (long long)r * sDD,
                                    pbkr + r * DD, pkrel, NN, DD, DD, 0, 0, 0, 0, 0);
        sgemm_bias_act<<<gq, 256>>>(x + (long long)st * sND, pWvr + (long long)r * sDD,
                                    pbvr + r * DD, pvreln, NN, DD, DD, 0, 0, 0, 0, 0);

        cudaMemsetAsync(pm, 0, sizeof(unsigned) * NN * HH, 0);
        cudaMemsetAsync(pz, 0, sizeof(float) * NN * HH, 0);

        edge_dot_kernel<<<(EE + 7) / 8, 256>>>(pQ + (long long)dt * sND, pkrel,
                                               esrc + r * EE, edst + r * EE, relbias, r);
        int ehThreads = EE * HH;
        seg_max_kernel<<<(ehThreads + 255) / 256, 256>>>(edst + r * EE);
        seg_exp_kernel<<<(ehThreads + 255) / 256, 256>>>(edst + r * EE);
        long long msgThreads = (long long)EE * 64;
        seg_msg_kernel<<<(unsigned)((msgThreads + 255) / 256), 256>>>(
            esrc + r * EE, edst + r * EE, pvreln, pagg + (long long)dt * sND);
    }

    // h = LN1(x + agg)
    ln_kernel<<<(TT * NN + 7) / 8, 256>>>(x, pagg, ln1_g, ln1_b, ph);

    // FFN
    dim3 gf1((NN + 127) / 128, D4 / 128, TT);
    sgemm_bias_act<<<gf1, 256>>>(ph, ffn_w1, ffn_b1, pf, NN, DD, D4,
                                 sND, (long long)DD * D4, D4, (long long)NN * D4, 1);
    dim3 gf2((NN + 127) / 128, DD / 128, TT);
    sgemm_bias_act<<<gf2, 256>>>(pf, ffn_w2, ffn_b2, pf2, NN, D4, DD,
                                 (long long)NN * D4, (long long)D4 * DD, DD, sND, 0);

    // out = LN2(h + f2)
    ln_kernel<<<(TT * NN + 7) / 8, 256>>>(ph, pf2, ln2_g, ln2_b, out);

    (void)in_sizes; (void)n_in; (void)out_size;
}

// round 6
// speedup vs baseline: 2.5701x; 1.7996x over previous
#include <cuda_runtime.h>
#include <cuda_bf16.h>
#include <math.h>
#include <stdint.h>

#define TT 4
#define NN 50000
#define DD 256
#define HH 8
#define RR 4
#define EE 200000
#define DK 32
#define D4 1024
#define K3Q (3*DD)    // 768
#define K3F (3*D4)    // 3072

// ---------------- scratch (device globals; allocation is forbidden) ----------------
__device__ __align__(16) float    g_Q[(size_t)TT*NN*DD];
__device__ __align__(16) float    g_krel[(size_t)NN*DD];
__device__ __align__(16) float    g_vreln[(size_t)NN*DD];
__device__ __align__(16) float    g_agg[(size_t)TT*NN*DD];
__device__ __align__(16) float    g_h[(size_t)TT*NN*DD];
__device__ __align__(16) float    g_f2[(size_t)TT*NN*DD];
__device__ __align__(16) float    g_logits[EE*HH];
__device__ __align__(16) float    g_p[EE*HH];
__device__ __align__(16) unsigned g_m[NN*HH];
__device__ __align__(16) float    g_z[NN*HH];
__device__ __align__(16) float    g_Wkr[RR*DD*DD];
__device__ __align__(16) float    g_Wvr[RR*DD*DD];
__device__ __align__(16) float    g_bkr[RR*DD];
__device__ __align__(16) float    g_bvr[RR*DD];
// bf16 split-tripled operands
__device__ __align__(256) __nv_bfloat16 g_x3[(size_t)TT*NN*K3Q];
__device__ __align__(256) __nv_bfloat16 g_h3[(size_t)TT*NN*K3Q];
__device__ __align__(256) __nv_bfloat16 g_f3[(size_t)TT*NN*K3F];
__device__ __align__(256) __nv_bfloat16 g_wq3[(size_t)TT*DD*K3Q];
__device__ __align__(256) __nv_bfloat16 g_wk3[(size_t)RR*DD*K3Q];
__device__ __align__(256) __nv_bfloat16 g_wv3[(size_t)RR*DD*K3Q];
__device__ __align__(256) __nv_bfloat16 g_w13[(size_t)TT*D4*K3Q];
__device__ __align__(256) __nv_bfloat16 g_w23[(size_t)TT*DD*K3F];

// ---------------- small helpers ----------------
__device__ __forceinline__ unsigned fenc(float f) {
    unsigned u = __float_as_uint(f);
    return (u & 0x80000000u) ? ~u : (u | 0x80000000u);
}
__device__ __forceinline__ float fdec(unsigned u) {
    unsigned b = (u & 0x80000000u) ? (u & 0x7FFFFFFFu) : ~u;
    return __uint_as_float(b);
}
__device__ __forceinline__ uint32_t smem_u32(const void* p) {
    return (uint32_t)__cvta_generic_to_shared(p);
}
__device__ __forceinline__ void cp16(uint32_t d, const void* g, int sz) {
    asm volatile("cp.async.cg.shared.global [%0], [%1], 16, %2;"
                 :: "r"(d), "l"(g), "r"(sz));
}
__device__ __forceinline__ void cp_commit() {
    asm volatile("cp.async.commit_group;");
}
__device__ __forceinline__ void ldm_x4(uint32_t* r, uint32_t a) {
    asm volatile("ldmatrix.sync.aligned.m8n8.x4.shared.b16 {%0,%1,%2,%3}, [%4];"
                 : "=r"(r[0]), "=r"(r[1]), "=r"(r[2]), "=r"(r[3]) : "r"(a));
}
__device__ __forceinline__ void mma16816(float* c, const uint32_t* a,
                                         uint32_t b0, uint32_t b1) {
    asm volatile(
        "mma.sync.aligned.m16n8k16.row.col.f32.bf16.bf16.f32 "
        "{%0,%1,%2,%3}, {%4,%5,%6,%7}, {%8,%9}, {%0,%1,%2,%3};"
        : "+f"(c[0]), "+f"(c[1]), "+f"(c[2]), "+f"(c[3])
        : "r"(a[0]), "r"(a[1]), "r"(a[2]), "r"(a[3]), "r"(b0), "r"(b1));
}

// ---------------- mma.sync split-bf16 GEMM ----------------
// C[m,n] = sum_k A3[m,k]*B3[n,k] (+bias[n]); BM=128, BN=128, BK=32, 4 stages.
// epi=0: fp32 out.  epi=1: gelu then tripled-bf16 out (for FFN1).
#define ROWB 80                       // 64B data + 16B pad (conflict-free ldmatrix)
#define STAGE_B (128*ROWB*2)          // A tile + B tile = 20480
#define GSMEM_TOTAL (4*STAGE_B)       // 81920

__global__ void __launch_bounds__(256, 2)
mma_gemm(const __nv_bfloat16* __restrict__ A3, const __nv_bfloat16* __restrict__ B3,
         const float* __restrict__ bias, float* __restrict__ Cout,
         __nv_bfloat16* __restrict__ C3out,
         int M, int K3, int Nout,
         long long sA, long long sB, long long sBias, long long sC, int epi)
{
    extern __shared__ __align__(128) char smem[];
    const int t = blockIdx.z;
    A3 += (long long)t * sA;
    B3 += (long long)t * sB;
    bias += (long long)t * sBias;
    if (Cout)  Cout  += (long long)t * sC;
    if (C3out) C3out += (long long)t * (3LL * sC);

    const uint32_t sb = smem_u32(smem);
    const int tid = threadIdx.x;
    const int wid = tid >> 5;
    const int lane = tid & 31;
    const int wm = wid >> 2;      // 0..1
    const int wn = wid & 3;       // 0..3

    const int bm = blockIdx.x * 128;
    const int bn = blockIdx.y * 128;
    const int NC = K3 >> 5;       // BK=32 chunks

    float acc[4][4][4];
#pragma unroll
    for (int i = 0; i < 4; i++)
#pragma unroll
        for (int j = 0; j < 4; j++)
#pragma unroll
            for (int c = 0; c < 4; c++) acc[i][j][c] = 0.f;

#define LOAD_CHUNK(ch) do {                                                    \
        int _slot = (ch) & 3;                                                  \
        uint32_t _ab = sb + _slot * STAGE_B;                                   \
        uint32_t _bb = _ab + 128 * ROWB;                                       \
        long long _k0 = (long long)(ch) << 5;                                  \
        for (int i = tid; i < 512; i += 256) {                                 \
            int row = i >> 2, c4 = i & 3;                                      \
            int gr = bm + row;                                                 \
            cp16(_ab + row * ROWB + c4 * 16,                                   \
                 A3 + (long long)gr * K3 + _k0 + c4 * 8, (gr < M) ? 16 : 0);   \
        }                                                                      \
        for (int i = tid; i < 512; i += 256) {                                 \
            int row = i >> 2, c4 = i & 3;                                      \
            cp16(_bb + row * ROWB + c4 * 16,                                   \
                 B3 + (long long)(bn + row) * K3 + _k0 + c4 * 8, 16);          \
        }                                                                      \
        cp_commit();                                                           \
    } while (0)

    // prefetch 3 stages
    LOAD_CHUNK(0); LOAD_CHUNK(1); LOAD_CHUNK(2);

    for (int j = 0; j < NC; j++) {
        int wg = NC - 1 - j; if (wg > 2) wg = 2;
        if (wg == 2)      asm volatile("cp.async.wait_group 2;");
        else if (wg == 1) asm volatile("cp.async.wait_group 1;");
        else              asm volatile("cp.async.wait_group 0;");
        __syncthreads();
        if (j + 3 < NC) LOAD_CHUNK(j + 3);

        const int slot = j & 3;
        const uint32_t aw = sb + slot * STAGE_B;
        const uint32_t bw = aw + 128 * ROWB;
#pragma unroll
        for (int kh = 0; kh < 2; kh++) {
            uint32_t afr[4][4];
#pragma unroll
            for (int mi = 0; mi < 4; mi++) {
                int row = wm * 64 + mi * 16 + (lane & 15);
                int col = kh * 16 + ((lane >> 4) << 3);
                ldm_x4(afr[mi], aw + row * ROWB + col * 2);
            }
            uint32_t bfr[2][4];
#pragma unroll
            for (int bi = 0; bi < 2; bi++) {
                int row = wn * 32 + bi * 16 + (lane & 15);
                int col = kh * 16 + ((lane >> 4) << 3);
                ldm_x4(bfr[bi], bw + row * ROWB + col * 2);
            }
#pragma unroll
            for (int mi = 0; mi < 4; mi++)
#pragma unroll
                for (int ni = 0; ni < 4; ni++) {
                    uint32_t b0 = bfr[ni >> 1][ni & 1];
                    uint32_t b1 = bfr[ni >> 1][(ni & 1) + 2];
                    mma16816(acc[mi][ni], afr[mi], b0, b1);
                }
        }
    }
#undef LOAD_CHUNK

    // ---- epilogue ----
#pragma unroll
    for (int mi = 0; mi < 4; mi++) {
#pragma unroll
        for (int half = 0; half < 2; half++) {
            int row = bm + wm * 64 + mi * 16 + (lane >> 2) + half * 8;
            if (row >= M) continue;
#pragma unroll
            for (int ni = 0; ni < 4; ni++) {
                int col = bn + wn * 32 + ni * 8 + ((lane & 3) << 1);
                float v0 = acc[mi][ni][half * 2 + 0] + bias[col + 0];
                float v1 = acc[mi][ni][half * 2 + 1] + bias[col + 1];
                if (epi == 0) {
                    float2 v = make_float2(v0, v1);
                    *(float2*)&Cout[(long long)row * Nout + col] = v;
                } else {
                    v0 = 0.5f * v0 * (1.f + erff(v0 * 0.7071067811865476f));
                    v1 = 0.5f * v1 * (1.f + erff(v1 * 0.7071067811865476f));
                    __nv_bfloat16 h0 = __float2bfloat16(v0);
                    __nv_bfloat16 h1 = __float2bfloat16(v1);
                    __nv_bfloat16 l0 = __float2bfloat16(v0 - __bfloat162float(h0));
                    __nv_bfloat16 l1 = __float2bfloat16(v1 - __bfloat162float(h1));
                    __nv_bfloat162 hp, lp;
                    hp.x = h0; hp.y = h1;
                    lp.x = l0; lp.y = l1;
                    __nv_bfloat16* rp = C3out + (long long)row * (3LL * Nout);
                    *(__nv_bfloat162*)&rp[col]            = hp;
                    *(__nv_bfloat162*)&rp[Nout + col]     = lp;
                    *(__nv_bfloat162*)&rp[2 * Nout + col] = hp;
                }
            }
        }
    }
}

// ---------------- weight fold (fp32) ----------------
__global__ void __launch_bounds__(256)
combine_w_kernel(const float* __restrict__ W, const float* __restrict__ Wrel,
                 float* __restrict__ outW, int st, int r)
{
    int idx = blockIdx.x * 256 + threadIdx.x;
    if (idx >= DD * DD) return;
    int d = idx >> 8;
    int c = idx & 255;
    int h = c >> 5, f = c & 31;
    const float* wrow = W + ((long long)st * DD + d) * DD + h * DK;
    const float* wr   = Wrel + ((long long)(r * HH + h) * DK) * DK + f;
    float s = 0.f;
#pragma unroll
    for (int k = 0; k < DK; k++) s = fmaf(wrow[k], wr[k * DK], s);
    outW[idx] = s;
}

__global__ void
combine_b_kernel(const float* __restrict__ b, const float* __restrict__ Wrel,
                 float* __restrict__ outb, int st, int r)
{
    int c = blockIdx.x * blockDim.x + threadIdx.x;
    if (c >= DD) return;
    int h = c >> 5, f = c & 31;
    const float* br = b + st * DD + h * DK;
    const float* wr = Wrel + ((long long)(r * HH + h) * DK) * DK + f;
    float s = 0.f;
#pragma unroll
    for (int k = 0; k < DK; k++) s = fmaf(br[k], wr[k * DK], s);
    outb[c] = s;
}

// ---------------- split-triple conversions ----------------
// A-side: A3[row][3K] = [hi | lo | hi]
__global__ void __launch_bounds__(256)
triple_a_kernel(const float* __restrict__ A, __nv_bfloat16* __restrict__ A3,
                long long total, int K)
{
    long long i = (long long)blockIdx.x * 256 + threadIdx.x;
    if (i >= total) return;
    long long row = i / K;
    int k = (int)(i - row * K);
    float v = A[i];
    __nv_bfloat16 hi = __float2bfloat16(v);
    __nv_bfloat16 lo = __float2bfloat16(v - __bfloat162float(hi));
    __nv_bfloat16* r = A3 + row * (3LL * K);
    r[k] = hi; r[K + k] = lo; r[2 * K + k] = hi;
}

// B-side with transpose: W[K][Nw] -> W3[Nw][3K] = [hi | hi | lo]
__global__ void __launch_bounds__(256)
triple_w_kernel(const float* __restrict__ W, __nv_bfloat16* __restrict__ W3,
                int K, int Nw)
{
    int i = blockIdx.x * 256 + threadIdx.x;
    if (i >= K * Nw) return;
    int k = i / Nw, n = i - k * Nw;
    float v = W[i];
    __nv_bfloat16 hi = __float2bfloat16(v);
    __nv_bfloat16 lo = __float2bfloat16(v - __bfloat162float(hi));
    __nv_bfloat16* r = W3 + (long long)n * (3LL * K);
    r[k] = hi; r[K + k] = hi; r[2 * K + k] = lo;
}

// ---------------- edge phase ----------------
__global__ void __launch_bounds__(256)
edge_dot_kernel(const float* __restrict__ Qbase, const float* __restrict__ Krel,
                const int* __restrict__ esrc, const int* __restrict__ edst,
                const float* __restrict__ rel_bias, int r)
{
    const int warp = threadIdx.x >> 5;
    const int lane = threadIdx.x & 31;
    const int h = lane >> 2, q = lane & 3;
    const float brel = rel_bias[r];
    int e = blockIdx.x * 8 + warp;
    if (e >= EE) return;
    int s = esrc[e];
    int d = edst[e];
    const float4* qp = (const float4*)&Qbase[(long long)d * DD + h * DK + q * 8];
    const float4* kp = (const float4*)&Krel[(long long)s * DD + h * DK + q * 8];
    float4 q0 = qp[0], q1 = qp[1];
    float4 k0 = kp[0], k1 = kp[1];
    float acc = q0.x * k0.x + q0.y * k0.y + q0.z * k0.z + q0.w * k0.w
              + q1.x * k1.x + q1.y * k1.y + q1.z * k1.z + q1.w * k1.w;
    acc += __shfl_xor_sync(0xffffffffu, acc, 1);
    acc += __shfl_xor_sync(0xffffffffu, acc, 2);
    if (q == 0) {
        float lg = acc * 0.17677669529663687f + brel;
        g_logits[e * HH + h] = lg;
        atomicMax(&g_m[d * HH + h], fenc(lg));
    }
}

__global__ void seg_exp_kernel(const int* __restrict__ edst)
{
    int i = blockIdx.x * blockDim.x + threadIdx.x;
    if (i >= EE * HH) return;
    int e = i >> 3;
    int h = i & 7;
    int d = edst[e];
    float m = fdec(g_m[d * HH + h]);
    float p = expf(g_logits[i] - m);
    g_p[i] = p;
    atomicAdd(&g_z[d * HH + h], p);
}

__global__ void __launch_bounds__(256)
seg_msg_kernel(const int* __restrict__ esrc, const int* __restrict__ edst,
               const float* __restrict__ Vrel, float* __restrict__ aggbase)
{
    long long i = (long long)blockIdx.x * 256 + threadIdx.x;  // over EE*64
    if (i >= (long long)EE * 64) return;
    int e = (int)(i >> 6);
    int w = (int)(i & 63);
    int c = w * 4;
    int h = c >> 5;
    int s = esrc[e];
    int d = edst[e];
    float attn = g_p[e * HH + h] / g_z[d * HH + h];
    float4 v = *(const float4*)&Vrel[(long long)s * DD + c];
    float* dst = &aggbase[(long long)d * DD + c];
    asm volatile("red.global.add.v4.f32 [%0], {%1,%2,%3,%4};"
                 :: "l"(dst), "f"(attn * v.x), "f"(attn * v.y),
                    "f"(attn * v.z), "f"(attn * v.w)
                 : "memory");
}

// ---------------- layernorm(residual) [+ optional tripled-bf16 out] ----------------
__global__ void __launch_bounds__(256)
ln_kernel(const float* __restrict__ X, const float* __restrict__ Res,
          const float* __restrict__ G, const float* __restrict__ B,
          float* __restrict__ Out, __nv_bfloat16* __restrict__ Out3)
{
    int row = blockIdx.x * 8 + (threadIdx.x >> 5);
    if (row >= TT * NN) return;
    int lane = threadIdx.x & 31;
    int t = row / NN;
    const float* xr = X + (long long)row * DD;
    const float* rr = Res + (long long)row * DD;
    float v[8];
    float sum = 0.f;
#pragma unroll
    for (int j = 0; j < 8; j++) {
        v[j] = xr[lane + 32 * j] + rr[lane + 32 * j];
        sum += v[j];
    }
#pragma unroll
    for (int o = 16; o > 0; o >>= 1) sum += __shfl_xor_sync(0xffffffffu, sum, o);
    float mu = sum * (1.f / 256.f);
    float var = 0.f;
#pragma unroll
    for (int j = 0; j < 8; j++) {
        float dlt = v[j] - mu;
        var = fmaf(dlt, dlt, var);
    }
#pragma unroll
    for (int o = 16; o > 0; o >>= 1) var += __shfl_xor_sync(0xffffffffu, var, o);
    float rstd = rsqrtf(var * (1.f / 256.f) + 1e-5f);
#pragma unroll
    for (int j = 0; j < 8; j++) {
        int c = lane + 32 * j;
        float y = (v[j] - mu) * rstd * G[t * DD + c] + B[t * DD + c];
        Out[(long long)row * DD + c] = y;
        if (Out3) {
            __nv_bfloat16 hi = __float2bfloat16(y);
            __nv_bfloat16 lo = __float2bfloat16(y - __bfloat162float(hi));
            __nv_bfloat16* r3 = Out3 + (long long)row * K3Q;
            r3[c] = hi; r3[DD + c] = lo; r3[2 * DD + c] = hi;
        }
    }
}

// ---------------- launch ----------------
extern "C" void kernel_launch(void* const* d_in, const int* in_sizes, int n_in,
                              void* d_out, int out_size)
{
    const float* x       = (const float*)d_in[0];
    const int*   esrc    = (const int*)d_in[1];
    const int*   edst    = (const int*)d_in[2];
    const float* Wq      = (const float*)d_in[3];
    const float* bq      = (const float*)d_in[4];
    const float* Wk      = (const float*)d_in[5];
    const float* bk      = (const float*)d_in[6];
    const float* Wv      = (const float*)d_in[7];
    const float* bv      = (const float*)d_in[8];
    const float* W_attn  = (const float*)d_in[9];
    const float* W_msg   = (const float*)d_in[10];
    const float* relbias = (const float*)d_in[11];
    const float* ln1_g   = (const float*)d_in[12];
    const float* ln1_b   = (const float*)d_in[13];
    const float* ln2_g   = (const float*)d_in[14];
    const float* ln2_b   = (const float*)d_in[15];
    const float* ffn_w1  = (const float*)d_in[16];
    const float* ffn_b1  = (const float*)d_in[17];
    const float* ffn_w2  = (const float*)d_in[18];
    const float* ffn_b2  = (const float*)d_in[19];
    float* out = (float*)d_out;

    float *pQ, *pkrel, *pvreln, *pagg, *ph, *pf2, *pz;
    float *pWkr, *pWvr, *pbkr, *pbvr;
    unsigned* pm;
    __nv_bfloat16 *px3, *ph3, *pf3, *pwq3, *pwk3, *pwv3, *pw13, *pw23;
    cudaGetSymbolAddress((void**)&pQ, g_Q);
    cudaGetSymbolAddress((void**)&pkrel, g_krel);
    cudaGetSymbolAddress((void**)&pvreln, g_vreln);
    cudaGetSymbolAddress((void**)&pagg, g_agg);
    cudaGetSymbolAddress((void**)&ph, g_h);
    cudaGetSymbolAddress((void**)&pf2, g_f2);
    cudaGetSymbolAddress((void**)&pm, g_m);
    cudaGetSymbolAddress((void**)&pz, g_z);
    cudaGetSymbolAddress((void**)&pWkr, g_Wkr);
    cudaGetSymbolAddress((void**)&pWvr, g_Wvr);
    cudaGetSymbolAddress((void**)&pbkr, g_bkr);
    cudaGetSymbolAddress((void**)&pbvr, g_bvr);
    cudaGetSymbolAddress((void**)&px3, g_x3);
    cudaGetSymbolAddress((void**)&ph3, g_h3);
    cudaGetSymbolAddress((void**)&pf3, g_f3);
    cudaGetSymbolAddress((void**)&pwq3, g_wq3);
    cudaGetSymbolAddress((void**)&pwk3, g_wk3);
    cudaGetSymbolAddress((void**)&pwv3, g_wv3);
    cudaGetSymbolAddress((void**)&pw13, g_w13);
    cudaGetSymbolAddress((void**)&pw23, g_w23);

    cudaFuncSetAttribute(mma_gemm, cudaFuncAttributeMaxDynamicSharedMemorySize, GSMEM_TOTAL);

    const long long sND = (long long)NN * DD;
    const long long sDD = (long long)DD * DD;
    const int stype[RR] = {1, 2, 3, 1};
    const int dtype[RR] = {0, 0, 3, 3};
    const int GMX = (NN + 127) / 128;   // 391

    // ---- weight prep ----
    for (int r = 0; r < RR; r++) {
        combine_w_kernel<<<(DD * DD + 255) / 256, 256>>>(Wk, W_attn, pWkr + (long long)r * sDD, stype[r], r);
        combine_w_kernel<<<(DD * DD + 255) / 256, 256>>>(Wv, W_msg, pWvr + (long long)r * sDD, stype[r], r);
        combine_b_kernel<<<1, DD>>>(bk, W_attn, pbkr + r * DD, stype[r], r);
        combine_b_kernel<<<1, DD>>>(bv, W_msg, pbvr + r * DD, stype[r], r);
    }
    // tripled bf16 weights
    triple_w_kernel<<<(DD * DD + 255) / 256, 256>>>(Wq + 0 * sDD, pwq3 + 0LL * DD * K3Q, DD, DD);
    triple_w_kernel<<<(DD * DD + 255) / 256, 256>>>(Wq + 3 * sDD, pwq3 + 3LL * DD * K3Q, DD, DD);
    for (int r = 0; r < RR; r++) {
        triple_w_kernel<<<(DD * DD + 255) / 256, 256>>>(pWkr + (long long)r * sDD, pwk3 + (long long)r * DD * K3Q, DD, DD);
        triple_w_kernel<<<(DD * DD + 255) / 256, 256>>>(pWvr + (long long)r * sDD, pwv3 + (long long)r * DD * K3Q, DD, DD);
    }
    for (int t = 0; t < TT; t++) {
        triple_w_kernel<<<(DD * D4 + 255) / 256, 256>>>(ffn_w1 + (long long)t * DD * D4, pw13 + (long long)t * D4 * K3Q, DD, D4);
        triple_w_kernel<<<(D4 * DD + 255) / 256, 256>>>(ffn_w2 + (long long)t * D4 * DD, pw23 + (long long)t * DD * K3F, D4, DD);
    }
    // tripled x
    {
        long long total = (long long)TT * NN * DD;
        triple_a_kernel<<<(unsigned)((total + 255) / 256), 256>>>(x, px3, total, DD);
    }

    // ---- Q projections (dst types 0 and 3) ----
    {
        dim3 g(GMX, DD / 128, 1);
        mma_gemm<<<g, 256, GSMEM_TOTAL>>>(px3 + 0LL * NN * K3Q, pwq3 + 0LL * DD * K3Q, bq + 0 * DD,
                                          pQ + 0 * sND, nullptr, NN, K3Q, DD, 0, 0, 0, 0, 0);
        mma_gemm<<<g, 256, GSMEM_TOTAL>>>(px3 + 3LL * NN * K3Q, pwq3 + 3LL * DD * K3Q, bq + 3 * DD,
                                          pQ + 3 * sND, nullptr, NN, K3Q, DD, 0, 0, 0, 0, 0);
    }

    cudaMemsetAsync(pagg, 0, sizeof(float) * TT * NN * DD, 0);

    for (int r = 0; r < RR; r++) {
        const int st = stype[r], dt = dtype[r];
        dim3 g(GMX, DD / 128, 1);
        mma_gemm<<<g, 256, GSMEM_TOTAL>>>(px3 + (long long)st * NN * K3Q, pwk3 + (long long)r * DD * K3Q,
                                          pbkr + r * DD, pkrel, nullptr, NN, K3Q, DD, 0, 0, 0, 0, 0);
        mma_gemm<<<g, 256, GSMEM_TOTAL>>>(px3 + (long long)st * NN * K3Q, pwv3 + (long long)r * DD * K3Q,
                                          pbvr + r * DD, pvreln, nullptr, NN, K3Q, DD, 0, 0, 0, 0, 0);

        cudaMemsetAsync(pm, 0, sizeof(unsigned) * NN * HH, 0);
        cudaMemsetAsync(pz, 0, sizeof(float) * NN * HH, 0);

        edge_dot_kernel<<<(EE + 7) / 8, 256>>>(pQ + (long long)dt * sND, pkrel,
                                               esrc + r * EE, edst + r * EE, relbias, r);
        seg_exp_kernel<<<(EE * HH + 255) / 256, 256>>>(edst + r * EE);
        long long msgThreads = (long long)EE * 64;
        seg_msg_kernel<<<(unsigned)((msgThreads + 255) / 256), 256>>>(
            esrc + r * EE, edst + r * EE, pvreln, pagg + (long long)dt * sND);
    }

    // h = LN1(x + agg), also produce tripled bf16 h3
    ln_kernel<<<(TT * NN + 7) / 8, 256>>>(x, pagg, ln1_g, ln1_b, ph, ph3);

    // FFN1: f3 = triple(gelu(h @ W1 + b1))  [no fp32 intermediate]
    {
        dim3 g(GMX, D4 / 128, TT);
        mma_gemm<<<g, 256, GSMEM_TOTAL>>>(ph3, pw13, ffn_b1, nullptr, pf3,
                                          NN, K3Q, D4,
                                          (long long)NN * K3Q, (long long)D4 * K3Q,
                                          D4, (long long)NN * D4, 1);
    }
    // FFN2: f2 = f3 @ W2 + b2
    {
        dim3 g(GMX, DD / 128, TT);
        mma_gemm<<<g, 256, GSMEM_TOTAL>>>(pf3, pw23, ffn_b2, pf2, nullptr,
                                          NN, K3F, DD,
                                          (long long)NN * K3F, (long long)DD * K3F,
                                          DD, sND, 0);
    }

    // out = LN2(h + f2)
    ln_kernel<<<(TT * NN + 7) / 8, 256>>>(ph, pf2, ln2_g, ln2_b, out, nullptr);

    (void)in_sizes; (void)n_in; (void)out_size;
}

// round 7
// speedup vs baseline: 2.6027x; 1.0127x over previous
#include <cuda_runtime.h>
#include <cuda_bf16.h>
#include <math.h>
#include <stdint.h>

#define TT 4
#define NN 50000
#define DD 256
#define HH 8
#define RR 4
#define EE 200000
#define DK 32
#define D4 1024
#define K3Q (3*DD)    // 768
#define K3F (3*D4)    // 3072

// ---------------- scratch (device globals; allocation is forbidden) ----------------
__device__ __align__(16) float    g_Q[(size_t)TT*NN*DD];
__device__ __align__(16) float    g_kv1[(size_t)NN*1024];   // st=1: [k_r0|v_r0|k_r3|v_r3]
__device__ __align__(16) float    g_kv2[(size_t)NN*512];    // st=2: [k_r1|v_r1]
__device__ __align__(16) float    g_kv3[(size_t)NN*512];    // st=3: [k_r2|v_r2]
__device__ __align__(16) float    g_agg[(size_t)TT*NN*DD];
__device__ __align__(16) float    g_h[(size_t)TT*NN*DD];
__device__ __align__(16) float    g_f2[(size_t)TT*NN*DD];
__device__ __align__(16) float    g_logits[(size_t)RR*EE*HH];
__device__ __align__(16) float    g_p[(size_t)RR*EE*HH];
__device__ __align__(16) unsigned g_m[(size_t)RR*NN*HH];
__device__ __align__(16) float    g_z[(size_t)RR*NN*HH];
__device__ __align__(16) float    g_Wkr[RR*DD*DD];
__device__ __align__(16) float    g_Wvr[RR*DD*DD];
__device__ __align__(16) float    g_bkv1[1024];
__device__ __align__(16) float    g_bkv2[512];
__device__ __align__(16) float    g_bkv3[512];
// bf16 split-tripled operands
__device__ __align__(256) __nv_bfloat16 g_x3[(size_t)TT*NN*K3Q];
__device__ __align__(256) __nv_bfloat16 g_h3[(size_t)TT*NN*K3Q];
__device__ __align__(256) __nv_bfloat16 g_f3[(size_t)TT*NN*K3F];
__device__ __align__(256) __nv_bfloat16 g_wq3[(size_t)TT*DD*K3Q];
__device__ __align__(256) __nv_bfloat16 g_wkv1[(size_t)1024*K3Q];
__device__ __align__(256) __nv_bfloat16 g_wkv2[(size_t)512*K3Q];
__device__ __align__(256) __nv_bfloat16 g_wkv3[(size_t)512*K3Q];
__device__ __align__(256) __nv_bfloat16 g_w13[(size_t)TT*D4*K3Q];
__device__ __align__(256) __nv_bfloat16 g_w23[(size_t)TT*DD*K3F];

// ---------------- small helpers ----------------
__device__ __forceinline__ unsigned fenc(float f) {
    unsigned u = __float_as_uint(f);
    return (u & 0x80000000u) ? ~u : (u | 0x80000000u);
}
__device__ __forceinline__ float fdec(unsigned u) {
    unsigned b = (u & 0x80000000u) ? (u & 0x7FFFFFFFu) : ~u;
    return __uint_as_float(b);
}
__device__ __forceinline__ uint32_t smem_u32(const void* p) {
    return (uint32_t)__cvta_generic_to_shared(p);
}
__device__ __forceinline__ void cp16(uint32_t d, const void* g, int sz) {
    asm volatile("cp.async.cg.shared.global [%0], [%1], 16, %2;"
                 :: "r"(d), "l"(g), "r"(sz));
}
__device__ __forceinline__ void cp_commit() {
    asm volatile("cp.async.commit_group;");
}
__device__ __forceinline__ void ldm_x4(uint32_t* r, uint32_t a) {
    asm volatile("ldmatrix.sync.aligned.m8n8.x4.shared.b16 {%0,%1,%2,%3}, [%4];"
                 : "=r"(r[0]), "=r"(r[1]), "=r"(r[2]), "=r"(r[3]) : "r"(a));
}
__device__ __forceinline__ void mma16816(float* c, const uint32_t* a,
                                         uint32_t b0, uint32_t b1) {
    asm volatile(
        "mma.sync.aligned.m16n8k16.row.col.f32.bf16.bf16.f32 "
        "{%0,%1,%2,%3}, {%4,%5,%6,%7}, {%8,%9}, {%0,%1,%2,%3};"
        : "+f"(c[0]), "+f"(c[1]), "+f"(c[2]), "+f"(c[3])
        : "r"(a[0]), "r"(a[1]), "r"(a[2]), "r"(a[3]), "r"(b0), "r"(b1));
}

// ---------------- mma.sync split-bf16 GEMM ----------------
#define ROWB 80
#define STAGE_B (128*ROWB*2)
#define GSMEM_TOTAL (4*STAGE_B)

__global__ void __launch_bounds__(256, 2)
mma_gemm(const __nv_bfloat16* __restrict__ A3, const __nv_bfloat16* __restrict__ B3,
         const float* __restrict__ bias, float* __restrict__ Cout,
         __nv_bfloat16* __restrict__ C3out,
         int M, int K3, int Nout,
         long long sA, long long sB, long long sBias, long long sC, int epi)
{
    extern __shared__ __align__(128) char smem[];
    const int t = blockIdx.z;
    A3 += (long long)t * sA;
    B3 += (long long)t * sB;
    bias += (long long)t * sBias;
    if (Cout)  Cout  += (long long)t * sC;
    if (C3out) C3out += (long long)t * (3LL * sC);

    const uint32_t sb = smem_u32(smem);
    const int tid = threadIdx.x;
    const int wid = tid >> 5;
    const int lane = tid & 31;
    const int wm = wid >> 2;
    const int wn = wid & 3;

    const int bm = blockIdx.x * 128;
    const int bn = blockIdx.y * 128;
    const int NC = K3 >> 5;

    float acc[4][4][4];
#pragma unroll
    for (int i = 0; i < 4; i++)
#pragma unroll
        for (int j = 0; j < 4; j++)
#pragma unroll
            for (int c = 0; c < 4; c++) acc[i][j][c] = 0.f;

#define LOAD_CHUNK(ch) do {                                                    \
        int _slot = (ch) & 3;                                                  \
        uint32_t _ab = sb + _slot * STAGE_B;                                   \
        uint32_t _bb = _ab + 128 * ROWB;                                       \
        long long _k0 = (long long)(ch) << 5;                                  \
        for (int i = tid; i < 512; i += 256) {                                 \
            int row = i >> 2, c4 = i & 3;                                      \
            int gr = bm + row;                                                 \
            cp16(_ab + row * ROWB + c4 * 16,                                   \
                 A3 + (long long)gr * K3 + _k0 + c4 * 8, (gr < M) ? 16 : 0);   \
        }                                                                      \
        for (int i = tid; i < 512; i += 256) {                                 \
            int row = i >> 2, c4 = i & 3;                                      \
            cp16(_bb + row * ROWB + c4 * 16,                                   \
                 B3 + (long long)(bn + row) * K3 + _k0 + c4 * 8, 16);          \
        }                                                                      \
        cp_commit();                                                           \
    } while (0)

    LOAD_CHUNK(0); LOAD_CHUNK(1); LOAD_CHUNK(2);

    for (int j = 0; j < NC; j++) {
        int wg = NC - 1 - j; if (wg > 2) wg = 2;
        if (wg == 2)      asm volatile("cp.async.wait_group 2;");
        else if (wg == 1) asm volatile("cp.async.wait_group 1;");
        else              asm volatile("cp.async.wait_group 0;");
        __syncthreads();
        if (j + 3 < NC) LOAD_CHUNK(j + 3);

        const int slot = j & 3;
        const uint32_t aw = sb + slot * STAGE_B;
        const uint32_t bw = aw + 128 * ROWB;
#pragma unroll
        for (int kh = 0; kh < 2; kh++) {
            uint32_t afr[4][4];
#pragma unroll
            for (int mi = 0; mi < 4; mi++) {
                int row = wm * 64 + mi * 16 + (lane & 15);
                int col = kh * 16 + ((lane >> 4) << 3);
                ldm_x4(afr[mi], aw + row * ROWB + col * 2);
            }
            uint32_t bfr[2][4];
#pragma unroll
            for (int bi = 0; bi < 2; bi++) {
                int row = wn * 32 + bi * 16 + (lane & 15);
                int col = kh * 16 + ((lane >> 4) << 3);
                ldm_x4(bfr[bi], bw + row * ROWB + col * 2);
            }
#pragma unroll
            for (int mi = 0; mi < 4; mi++)
#pragma unroll
                for (int ni = 0; ni < 4; ni++) {
                    uint32_t b0 = bfr[ni >> 1][ni & 1];
                    uint32_t b1 = bfr[ni >> 1][(ni & 1) + 2];
                    mma16816(acc[mi][ni], afr[mi], b0, b1);
                }
        }
    }
#undef LOAD_CHUNK

#pragma unroll
    for (int mi = 0; mi < 4; mi++) {
#pragma unroll
        for (int half = 0; half < 2; half++) {
            int row = bm + wm * 64 + mi * 16 + (lane >> 2) + half * 8;
            if (row >= M) continue;
#pragma unroll
            for (int ni = 0; ni < 4; ni++) {
                int col = bn + wn * 32 + ni * 8 + ((lane & 3) << 1);
                float v0 = acc[mi][ni][half * 2 + 0] + bias[col + 0];
                float v1 = acc[mi][ni][half * 2 + 1] + bias[col + 1];
                if (epi == 0) {
                    float2 v = make_float2(v0, v1);
                    *(float2*)&Cout[(long long)row * Nout + col] = v;
                } else {
                    v0 = 0.5f * v0 * (1.f + erff(v0 * 0.7071067811865476f));
                    v1 = 0.5f * v1 * (1.f + erff(v1 * 0.7071067811865476f));
                    __nv_bfloat16 h0 = __float2bfloat16(v0);
                    __nv_bfloat16 h1 = __float2bfloat16(v1);
                    __nv_bfloat16 l0 = __float2bfloat16(v0 - __bfloat162float(h0));
                    __nv_bfloat16 l1 = __float2bfloat16(v1 - __bfloat162float(h1));
                    __nv_bfloat162 hp, lp;
                    hp.x = h0; hp.y = h1;
                    lp.x = l0; lp.y = l1;
                    __nv_bfloat16* rp = C3out + (long long)row * (3LL * Nout);
                    *(__nv_bfloat162*)&rp[col]            = hp;
                    *(__nv_bfloat162*)&rp[Nout + col]     = lp;
                    *(__nv_bfloat162*)&rp[2 * Nout + col] = hp;
                }
            }
        }
    }
}

// ---------------- weight fold (fp32) ----------------
__global__ void __launch_bounds__(256)
combine_w_kernel(const float* __restrict__ W, const float* __restrict__ Wrel,
                 float* __restrict__ outW, int st, int r)
{
    int idx = blockIdx.x * 256 + threadIdx.x;
    if (idx >= DD * DD) return;
    int d = idx >> 8;
    int c = idx & 255;
    int h = c >> 5, f = c & 31;
    const float* wrow = W + ((long long)st * DD + d) * DD + h * DK;
    const float* wr   = Wrel + ((long long)(r * HH + h) * DK) * DK + f;
    float s = 0.f;
#pragma unroll
    for (int k = 0; k < DK; k++) s = fmaf(wrow[k], wr[k * DK], s);
    outW[idx] = s;
}

__global__ void
combine_b_kernel(const float* __restrict__ b, const float* __restrict__ Wrel,
                 float* __restrict__ outb, int st, int r)
{
    int c = blockIdx.x * blockDim.x + threadIdx.x;
    if (c >= DD) return;
    int h = c >> 5, f = c & 31;
    const float* br = b + st * DD + h * DK;
    const float* wr = Wrel + ((long long)(r * HH + h) * DK) * DK + f;
    float s = 0.f;
#pragma unroll
    for (int k = 0; k < DK; k++) s = fmaf(br[k], wr[k * DK], s);
    outb[c] = s;
}

// ---------------- split-triple conversions ----------------
__global__ void __launch_bounds__(256)
triple_a_kernel(const float* __restrict__ A, __nv_bfloat16* __restrict__ A3,
                long long total, int K)
{
    long long i = (long long)blockIdx.x * 256 + threadIdx.x;
    if (i >= total) return;
    long long row = i / K;
    int k = (int)(i - row * K);
    float v = A[i];
    __nv_bfloat16 hi = __float2bfloat16(v);
    __nv_bfloat16 lo = __float2bfloat16(v - __bfloat162float(hi));
    __nv_bfloat16* r = A3 + row * (3LL * K);
    r[k] = hi; r[K + k] = lo; r[2 * K + k] = hi;
}

// W[K][Nw] -> W3[Nw][3K] = [hi | hi | lo]
__global__ void __launch_bounds__(256)
triple_w_kernel(const float* __restrict__ W, __nv_bfloat16* __restrict__ W3,
                int K, int Nw)
{
    int i = blockIdx.x * 256 + threadIdx.x;
    if (i >= K * Nw) return;
    int k = i / Nw, n = i - k * Nw;
    float v = W[i];
    __nv_bfloat16 hi = __float2bfloat16(v);
    __nv_bfloat16 lo = __float2bfloat16(v - __bfloat162float(hi));
    __nv_bfloat16* r = W3 + (long long)n * (3LL * K);
    r[k] = hi; r[K + k] = hi; r[2 * K + k] = lo;
}

// ---------------- merged edge phase across all relations ----------------
// per-relation tables (compile-time)
__device__ __constant__ int c_dt[RR]    = {0, 0, 3, 3};
__device__ __constant__ int c_pitch[RR] = {1024, 512, 512, 1024};
__device__ __constant__ int c_koff[RR]  = {0, 0, 0, 512};
__device__ __constant__ int c_voff[RR]  = {256, 256, 256, 768};

__device__ __forceinline__ const float* kv_base(int r, const float* kv1,
                                                const float* kv2, const float* kv3) {
    return (r == 1) ? kv2 : (r == 2) ? kv3 : kv1;
}

__global__ void __launch_bounds__(256)
edge_dot_all(const float* __restrict__ Q, const float* __restrict__ kv1,
             const float* __restrict__ kv2, const float* __restrict__ kv3,
             const int* __restrict__ esrc, const int* __restrict__ edst,
             const float* __restrict__ rel_bias)
{
    const int warp = threadIdx.x >> 5;
    const int lane = threadIdx.x & 31;
    const int h = lane >> 2, q = lane & 3;
    long long ge = (long long)blockIdx.x * 8 + warp;
    if (ge >= (long long)RR * EE) return;
    int r = (int)(ge / EE);
    int s = esrc[ge];
    int d = edst[ge];
    const float* kb = kv_base(r, kv1, kv2, kv3);
    const float4* qp = (const float4*)&Q[((long long)c_dt[r] * NN + d) * DD + h * DK + q * 8];
    const float4* kp = (const float4*)&kb[(long long)s * c_pitch[r] + c_koff[r] + h * DK + q * 8];
    float4 q0 = qp[0], q1 = qp[1];
    float4 k0 = kp[0], k1 = kp[1];
    float acc = q0.x * k0.x + q0.y * k0.y + q0.z * k0.z + q0.w * k0.w
              + q1.x * k1.x + q1.y * k1.y + q1.z * k1.z + q1.w * k1.w;
    acc += __shfl_xor_sync(0xffffffffu, acc, 1);
    acc += __shfl_xor_sync(0xffffffffu, acc, 2);
    if (q == 0) {
        float lg = acc * 0.17677669529663687f + rel_bias[r];
        g_logits[ge * HH + h] = lg;
        atomicMax(&g_m[((long long)r * NN + d) * HH + h], fenc(lg));
    }
}

__global__ void __launch_bounds__(256)
seg_exp_all(const int* __restrict__ edst)
{
    long long i = (long long)blockIdx.x * 256 + threadIdx.x;
    if (i >= (long long)RR * EE * HH) return;
    long long ge = i >> 3;
    int h = (int)(i & 7);
    int r = (int)(ge / EE);
    int d = edst[ge];
    long long mz = ((long long)r * NN + d) * HH + h;
    float m = fdec(g_m[mz]);
    float p = expf(g_logits[i] - m);
    g_p[i] = p;
    atomicAdd(&g_z[mz], p);
}

__global__ void __launch_bounds__(256)
seg_msg_all(const int* __restrict__ esrc, const int* __restrict__ edst,
            const float* __restrict__ kv1, const float* __restrict__ kv2,
            const float* __restrict__ kv3, float* __restrict__ agg)
{
    long long i = (long long)blockIdx.x * 256 + threadIdx.x;   // RR*EE*64
    if (i >= (long long)RR * EE * 64) return;
    long long ge = i >> 6;
    int c = (int)(i & 63) * 4;
    int h = c >> 5;
    int r = (int)(ge / EE);
    int s = esrc[ge];
    int d = edst[ge];
    float attn = g_p[ge * HH + h] / g_z[((long long)r * NN + d) * HH + h];
    const float* vb = kv_base(r, kv1, kv2, kv3);
    float4 v = *(const float4*)&vb[(long long)s * c_pitch[r] + c_voff[r] + c];
    float* dst = &agg[((long long)c_dt[r] * NN + d) * DD + c];
    asm volatile("red.global.add.v4.f32 [%0], {%1,%2,%3,%4};"
                 :: "l"(dst), "f"(attn * v.x), "f"(attn * v.y),
                    "f"(attn * v.z), "f"(attn * v.w)
                 : "memory");
}

// ---------------- layernorm(residual) [+ optional tripled-bf16 out] ----------------
__global__ void __launch_bounds__(256)
ln_kernel(const float* __restrict__ X, const float* __restrict__ Res,
          const float* __restrict__ G, const float* __restrict__ B,
          float* __restrict__ Out, __nv_bfloat16* __restrict__ Out3)
{
    int row = blockIdx.x * 8 + (threadIdx.x >> 5);
    if (row >= TT * NN) return;
    int lane = threadIdx.x & 31;
    int t = row / NN;
    const float* xr = X + (long long)row * DD;
    const float* rr = Res + (long long)row * DD;
    float v[8];
    float sum = 0.f;
#pragma unroll
    for (int j = 0; j < 8; j++) {
        v[j] = xr[lane + 32 * j] + rr[lane + 32 * j];
        sum += v[j];
    }
#pragma unroll
    for (int o = 16; o > 0; o >>= 1) sum += __shfl_xor_sync(0xffffffffu, sum, o);
    float mu = sum * (1.f / 256.f);
    float var = 0.f;
#pragma unroll
    for (int j = 0; j < 8; j++) {
        float dlt = v[j] - mu;
        var = fmaf(dlt, dlt, var);
    }
#pragma unroll
    for (int o = 16; o > 0; o >>= 1) var += __shfl_xor_sync(0xffffffffu, var, o);
    float rstd = rsqrtf(var * (1.f / 256.f) + 1e-5f);
#pragma unroll
    for (int j = 0; j < 8; j++) {
        int c = lane + 32 * j;
        float y = (v[j] - mu) * rstd * G[t * DD + c] + B[t * DD + c];
        Out[(long long)row * DD + c] = y;
        if (Out3) {
            __nv_bfloat16 hi = __float2bfloat16(y);
            __nv_bfloat16 lo = __float2bfloat16(y - __bfloat162float(hi));
            __nv_bfloat16* r3 = Out3 + (long long)row * K3Q;
            r3[c] = hi; r3[DD + c] = lo; r3[2 * DD + c] = hi;
        }
    }
}

// ---------------- launch ----------------
extern "C" void kernel_launch(void* const* d_in, const int* in_sizes, int n_in,
                              void* d_out, int out_size)
{
    const float* x       = (const float*)d_in[0];
    const int*   esrc    = (const int*)d_in[1];
    const int*   edst    = (const int*)d_in[2];
    const float* Wq      = (const float*)d_in[3];
    const float* bq      = (const float*)d_in[4];
    const float* Wk      = (const float*)d_in[5];
    const float* bk      = (const float*)d_in[6];
    const float* Wv      = (const float*)d_in[7];
    const float* bv      = (const float*)d_in[8];
    const float* W_attn  = (const float*)d_in[9];
    const float* W_msg   = (const float*)d_in[10];
    const float* relbias = (const float*)d_in[11];
    const float* ln1_g   = (const float*)d_in[12];
    const float* ln1_b   = (const float*)d_in[13];
    const float* ln2_g   = (const float*)d_in[14];
    const float* ln2_b   = (const float*)d_in[15];
    const float* ffn_w1  = (const float*)d_in[16];
    const float* ffn_b1  = (const float*)d_in[17];
    const float* ffn_w2  = (const float*)d_in[18];
    const float* ffn_b2  = (const float*)d_in[19];
    float* out = (float*)d_out;

    float *pQ, *pkv1, *pkv2, *pkv3, *pagg, *ph, *pf2, *pz;
    float *pWkr, *pWvr, *pbkv1, *pbkv2, *pbkv3;
    unsigned* pm;
    __nv_bfloat16 *px3, *ph3, *pf3, *pwq3, *pwkv1, *pwkv2, *pwkv3, *pw13, *pw23;
    cudaGetSymbolAddress((void**)&pQ, g_Q);
    cudaGetSymbolAddress((void**)&pkv1, g_kv1);
    cudaGetSymbolAddress((void**)&pkv2, g_kv2);
    cudaGetSymbolAddress((void**)&pkv3, g_kv3);
    cudaGetSymbolAddress((void**)&pagg, g_agg);
    cudaGetSymbolAddress((void**)&ph, g_h);
    cudaGetSymbolAddress((void**)&pf2, g_f2);
    cudaGetSymbolAddress((void**)&pm, g_m);
    cudaGetSymbolAddress((void**)&pz, g_z);
    cudaGetSymbolAddress((void**)&pWkr, g_Wkr);
    cudaGetSymbolAddress((void**)&pWvr, g_Wvr);
    cudaGetSymbolAddress((void**)&pbkv1, g_bkv1);
    cudaGetSymbolAddress((void**)&pbkv2, g_bkv2);
    cudaGetSymbolAddress((void**)&pbkv3, g_bkv3);
    cudaGetSymbolAddress((void**)&px3, g_x3);
    cudaGetSymbolAddress((void**)&ph3, g_h3);
    cudaGetSymbolAddress((void**)&pf3, g_f3);
    cudaGetSymbolAddress((void**)&pwq3, g_wq3);
    cudaGetSymbolAddress((void**)&pwkv1, g_wkv1);
    cudaGetSymbolAddress((void**)&pwkv2, g_wkv2);
    cudaGetSymbolAddress((void**)&pwkv3, g_wkv3);
    cudaGetSymbolAddress((void**)&pw13, g_w13);
    cudaGetSymbolAddress((void**)&pw23, g_w23);

    cudaFuncSetAttribute(mma_gemm, cudaFuncAttributeMaxDynamicSharedMemorySize, GSMEM_TOTAL);

    const long long sND = (long long)NN * DD;
    const long long sDD = (long long)DD * DD;
    const int stype[RR] = {1, 2, 3, 1};
    const int GMX = (NN + 127) / 128;   // 391
    const int CW = (DD * DD + 255) / 256;

    // launches 0-4: prereqs for the profiled GEMM at launch #5
    {
        long long total = (long long)TT * NN * DD;
        triple_a_kernel<<<(unsigned)((total + 255) / 256), 256>>>(x, px3, total, DD);   // 0
    }
    triple_w_kernel<<<CW, 256>>>(Wq + 0 * sDD, pwq3 + 0LL * DD * K3Q, DD, DD);          // 1
    triple_w_kernel<<<CW, 256>>>(Wq + 3 * sDD, pwq3 + 3LL * DD * K3Q, DD, DD);          // 2
    combine_w_kernel<<<CW, 256>>>(Wk, W_attn, pWkr + 0LL * sDD, stype[0], 0);           // 3
    combine_w_kernel<<<CW, 256>>>(Wv, W_msg, pWvr + 0LL * sDD, stype[0], 0);            // 4
    // launch #5: representative GEMM (ncu -s 5 -c 1 profiles this)
    {
        dim3 g(GMX, DD / 128, 1);
        mma_gemm<<<g, 256, GSMEM_TOTAL>>>(px3 + 0LL * NN * K3Q, pwq3 + 0LL * DD * K3Q,  // 5
                                          bq + 0 * DD, pQ + 0 * sND, nullptr,
                                          NN, K3Q, DD, 0, 0, 0, 0, 0);
    }

    // remaining weight folds
    for (int r = 1; r < RR; r++) {
        combine_w_kernel<<<CW, 256>>>(Wk, W_attn, pWkr + (long long)r * sDD, stype[r], r);
        combine_w_kernel<<<CW, 256>>>(Wv, W_msg, pWvr + (long long)r * sDD, stype[r], r);
    }
    // biases into concatenated buffers
    combine_b_kernel<<<1, DD>>>(bk, W_attn, pbkv1 + 0,   stype[0], 0);
    combine_b_kernel<<<1, DD>>>(bv, W_msg,  pbkv1 + 256, stype[0], 0);
    combine_b_kernel<<<1, DD>>>(bk, W_attn, pbkv1 + 512, stype[3], 3);
    combine_b_kernel<<<1, DD>>>(bv, W_msg,  pbkv1 + 768, stype[3], 3);
    combine_b_kernel<<<1, DD>>>(bk, W_attn, pbkv2 + 0,   stype[1], 1);
    combine_b_kernel<<<1, DD>>>(bv, W_msg,  pbkv2 + 256, stype[1], 1);
    combine_b_kernel<<<1, DD>>>(bk, W_attn, pbkv3 + 0,   stype[2], 2);
    combine_b_kernel<<<1, DD>>>(bv, W_msg,  pbkv3 + 256, stype[2], 2);
    // tripled weights into concatenated buffers
    triple_w_kernel<<<CW, 256>>>(pWkr + 0LL * sDD, pwkv1 + 0LL   * K3Q, DD, DD);  // r0 k
    triple_w_kernel<<<CW, 256>>>(pWvr + 0LL * sDD, pwkv1 + 256LL * K3Q, DD, DD);  // r0 v
    triple_w_kernel<<<CW, 256>>>(pWkr + 3LL * sDD, pwkv1 + 512LL * K3Q, DD, DD);  // r3 k
    triple_w_kernel<<<CW, 256>>>(pWvr + 3LL * sDD, pwkv1 + 768LL * K3Q, DD, DD);  // r3 v
    triple_w_kernel<<<CW, 256>>>(pWkr + 1LL * sDD, pwkv2 + 0LL   * K3Q, DD, DD);  // r1 k
    triple_w_kernel<<<CW, 256>>>(pWvr + 1LL * sDD, pwkv2 + 256LL * K3Q, DD, DD);  // r1 v
    triple_w_kernel<<<CW, 256>>>(pWkr + 2LL * sDD, pwkv3 + 0LL   * K3Q, DD, DD);  // r2 k
    triple_w_kernel<<<CW, 256>>>(pWvr + 2LL * sDD, pwkv3 + 256LL * K3Q, DD, DD);  // r2 v
    for (int t = 0; t < TT; t++) {
        triple_w_kernel<<<(DD * D4 + 255) / 256, 256>>>(ffn_w1 + (long long)t * DD * D4,
                                                        pw13 + (long long)t * D4 * K3Q, DD, D4);
        triple_w_kernel<<<(D4 * DD + 255) / 256, 256>>>(ffn_w2 + (long long)t * D4 * DD,
                                                        pw23 + (long long)t * DD * K3F, D4, DD);
    }

    // Q projection for dst type 3
    {
        dim3 g(GMX, DD / 128, 1);
        mma_gemm<<<g, 256, GSMEM_TOTAL>>>(px3 + 3LL * NN * K3Q, pwq3 + 3LL * DD * K3Q,
                                          bq + 3 * DD, pQ + 3 * sND, nullptr,
                                          NN, K3Q, DD, 0, 0, 0, 0, 0);
    }
    // batched K/V GEMMs per source type
    {
        dim3 g1(GMX, 1024 / 128, 1);
        mma_gemm<<<g1, 256, GSMEM_TOTAL>>>(px3 + 1LL * NN * K3Q, pwkv1, pbkv1, pkv1, nullptr,
                                           NN, K3Q, 1024, 0, 0, 0, 0, 0);
        dim3 g2(GMX, 512 / 128, 1);
        mma_gemm<<<g2, 256, GSMEM_TOTAL>>>(px3 + 2LL * NN * K3Q, pwkv2, pbkv2, pkv2, nullptr,
                                           NN, K3Q, 512, 0, 0, 0, 0, 0);
        mma_gemm<<<g2, 256, GSMEM_TOTAL>>>(px3 + 3LL * NN * K3Q, pwkv3, pbkv3, pkv3, nullptr,
                                           NN, K3Q, 512, 0, 0, 0, 0, 0);
    }

    // edge phase (all relations in one pass)
    cudaMemsetAsync(pagg, 0, sizeof(float) * TT * NN * DD, 0);
    cudaMemsetAsync(pm, 0, sizeof(unsigned) * RR * NN * HH, 0);
    cudaMemsetAsync(pz, 0, sizeof(float) * RR * NN * HH, 0);
    {
        long long ne = (long long)RR * EE;
        edge_dot_all<<<(unsigned)((ne + 7) / 8), 256>>>(pQ, pkv1, pkv2, pkv3, esrc, edst, relbias);
        long long nh = ne * HH;
        seg_exp_all<<<(unsigned)((nh + 255) / 256), 256>>>(edst);
        long long nm = ne * 64;
        seg_msg_all<<<(unsigned)((nm + 255) / 256), 256>>>(esrc, edst, pkv1, pkv2, pkv3, pagg);
    }

    // h = LN1(x + agg) (+ tripled h3)
    ln_kernel<<<(TT * NN + 7) / 8, 256>>>(x, pagg, ln1_g, ln1_b, ph, ph3);

    // FFN1: f3 = triple(gelu(h @ W1 + b1))
    {
        dim3 g(GMX, D4 / 128, TT);
        mma_gemm<<<g, 256, GSMEM_TOTAL>>>(ph3, pw13, ffn_b1, nullptr, pf3,
                                          NN, K3Q, D4,
                                          (long long)NN * K3Q, (long long)D4 * K3Q,
                                          D4, (long long)NN * D4, 1);
    }
    // FFN2: f2 = f3 @ W2 + b2
    {
        dim3 g(GMX, DD / 128, TT);
        mma_gemm<<<g, 256, GSMEM_TOTAL>>>(pf3, pw23, ffn_b2, pf2, nullptr,
                                          NN, K3F, DD,
                                          (long long)NN * K3F, (long long)DD * K3F,
                                          DD, sND, 0);
    }

    // out = LN2(h + f2)
    ln_kernel<<<(TT * NN + 7) / 8, 256>>>(ph, pf2, ln2_g, ln2_b, out, nullptr);

    (void)in_sizes; (void)n_in; (void)out_size;
}

// round 8
// speedup vs baseline: 3.4835x; 1.3384x over previous
#include <cuda_runtime.h>
#include <cuda_fp16.h>
#include <cuda_bf16.h>
#include <math.h>
#include <stdint.h>

#define TT 4
#define NN 50000
#define DD 256
#define HH 8
#define RR 4
#define EE 200000
#define DK 32
#define D4 1024
#define K2Q (2*DD)    // 512
#define K2F (2*D4)    // 2048

// ---------------- scratch (device globals; allocation is forbidden) ----------------
__device__ __align__(16) float    g_Q[(size_t)TT*NN*DD];
__device__ __align__(16) float    g_kv1[(size_t)NN*1024];   // st=1: [k_r0|v_r0|k_r3|v_r3]
__device__ __align__(16) float    g_kv2[(size_t)NN*512];    // st=2: [k_r1|v_r1]
__device__ __align__(16) float    g_kv3[(size_t)NN*512];    // st=3: [k_r2|v_r2]
__device__ __align__(16) float    g_agg[(size_t)TT*NN*DD];
__device__ __align__(16) float    g_h[(size_t)TT*NN*DD];
__device__ __align__(16) float    g_f2[(size_t)TT*NN*DD];
__device__ __align__(16) float    g_logits[(size_t)RR*EE*HH];
__device__ __align__(16) float    g_p[(size_t)RR*EE*HH];
__device__ __align__(16) unsigned g_m[(size_t)RR*NN*HH];
__device__ __align__(16) float    g_z[(size_t)RR*NN*HH];
__device__ __align__(16) float    g_Wkr[RR*DD*DD];
__device__ __align__(16) float    g_Wvr[RR*DD*DD];
__device__ __align__(16) float    g_bkv1[1024];
__device__ __align__(16) float    g_bkv2[512];
__device__ __align__(16) float    g_bkv3[512];
// fp16 split-pair operands (A=[hi|lo], B=[hi|hi])
__device__ __align__(256) __half g_x2[(size_t)TT*NN*K2Q];
__device__ __align__(256) __half g_h2[(size_t)TT*NN*K2Q];
__device__ __align__(256) __half g_fh[(size_t)TT*NN*K2F];
__device__ __align__(256) __half g_wq2[(size_t)TT*DD*K2Q];
__device__ __align__(256) __half g_wkv1[(size_t)1024*K2Q];
__device__ __align__(256) __half g_wkv2[(size_t)512*K2Q];
__device__ __align__(256) __half g_wkv3[(size_t)512*K2Q];
__device__ __align__(256) __half g_w12[(size_t)TT*D4*K2Q];
__device__ __align__(256) __half g_w22[(size_t)TT*DD*K2F];

// ---------------- small helpers ----------------
__device__ __forceinline__ unsigned fenc(float f) {
    unsigned u = __float_as_uint(f);
    return (u & 0x80000000u) ? ~u : (u | 0x80000000u);
}
__device__ __forceinline__ float fdec(unsigned u) {
    unsigned b = (u & 0x80000000u) ? (u & 0x7FFFFFFFu) : ~u;
    return __uint_as_float(b);
}
__device__ __forceinline__ uint32_t smem_u32(const void* p) {
    return (uint32_t)__cvta_generic_to_shared(p);
}
__device__ __forceinline__ void cp16(uint32_t d, const void* g, int sz) {
    asm volatile("cp.async.cg.shared.global [%0], [%1], 16, %2;"
                 :: "r"(d), "l"(g), "r"(sz));
}
__device__ __forceinline__ void cp_commit() {
    asm volatile("cp.async.commit_group;");
}
__device__ __forceinline__ void ldm_x4(uint32_t* r, uint32_t a) {
    asm volatile("ldmatrix.sync.aligned.m8n8.x4.shared.b16 {%0,%1,%2,%3}, [%4];"
                 : "=r"(r[0]), "=r"(r[1]), "=r"(r[2]), "=r"(r[3]) : "r"(a));
}
__device__ __forceinline__ void mma16816(float* c, const uint32_t* a,
                                         uint32_t b0, uint32_t b1) {
    asm volatile(
        "mma.sync.aligned.m16n8k16.row.col.f32.f16.f16.f32 "
        "{%0,%1,%2,%3}, {%4,%5,%6,%7}, {%8,%9}, {%0,%1,%2,%3};"
        : "+f"(c[0]), "+f"(c[1]), "+f"(c[2]), "+f"(c[3])
        : "r"(a[0]), "r"(a[1]), "r"(a[2]), "r"(a[3]), "r"(b0), "r"(b1));
}

// ---------------- mma.sync split-fp16 GEMM ----------------
#define ROWB 80
#define STAGE_B (128*ROWB*2)
#define GSMEM_TOTAL (4*STAGE_B)

__global__ void __launch_bounds__(256, 2)
mma_gemm(const __half* __restrict__ A2, const __half* __restrict__ B2,
         const float* __restrict__ bias, float* __restrict__ Cout,
         __half* __restrict__ C2out,
         int M, int K2, int Nout,
         long long sA, long long sB, long long sBias, long long sC, int epi)
{
    extern __shared__ __align__(128) char smem[];
    const int t = blockIdx.z;
    A2 += (long long)t * sA;
    B2 += (long long)t * sB;
    bias += (long long)t * sBias;
    if (Cout)  Cout  += (long long)t * sC;
    if (C2out) C2out += (long long)t * (2LL * sC);

    const uint32_t sb = smem_u32(smem);
    const int tid = threadIdx.x;
    const int wid = tid >> 5;
    const int lane = tid & 31;
    const int wm = wid >> 2;
    const int wn = wid & 3;

    const int bm = blockIdx.x * 128;
    const int bn = blockIdx.y * 128;
    const int NC = K2 >> 5;

    float acc[4][4][4];
#pragma unroll
    for (int i = 0; i < 4; i++)
#pragma unroll
        for (int j = 0; j < 4; j++)
#pragma unroll
            for (int c = 0; c < 4; c++) acc[i][j][c] = 0.f;

#define LOAD_CHUNK(ch) do {                                                    \
        int _slot = (ch) & 3;                                                  \
        uint32_t _ab = sb + _slot * STAGE_B;                                   \
        uint32_t _bb = _ab + 128 * ROWB;                                       \
        long long _k0 = (long long)(ch) << 5;                                  \
        for (int i = tid; i < 512; i += 256) {                                 \
            int row = i >> 2, c4 = i & 3;                                      \
            int gr = bm + row;                                                 \
            cp16(_ab + row * ROWB + c4 * 16,                                   \
                 A2 + (long long)gr * K2 + _k0 + c4 * 8, (gr < M) ? 16 : 0);   \
        }                                                                      \
        for (int i = tid; i < 512; i += 256) {                                 \
            int row = i >> 2, c4 = i & 3;                                      \
            cp16(_bb + row * ROWB + c4 * 16,                                   \
                 B2 + (long long)(bn + row) * K2 + _k0 + c4 * 8, 16);          \
        }                                                                      \
        cp_commit();                                                           \
    } while (0)

    LOAD_CHUNK(0); LOAD_CHUNK(1); LOAD_CHUNK(2);

    for (int j = 0; j < NC; j++) {
        int wg = NC - 1 - j; if (wg > 2) wg = 2;
        if (wg == 2)      asm volatile("cp.async.wait_group 2;");
        else if (wg == 1) asm volatile("cp.async.wait_group 1;");
        else              asm volatile("cp.async.wait_group 0;");
        __syncthreads();
        if (j + 3 < NC) LOAD_CHUNK(j + 3);

        const int slot = j & 3;
        const uint32_t aw = sb + slot * STAGE_B;
        const uint32_t bw = aw + 128 * ROWB;
#pragma unroll
        for (int kh = 0; kh < 2; kh++) {
            uint32_t afr[4][4];
#pragma unroll
            for (int mi = 0; mi < 4; mi++) {
                int row = wm * 64 + mi * 16 + (lane & 15);
                int col = kh * 16 + ((lane >> 4) << 3);
                ldm_x4(afr[mi], aw + row * ROWB + col * 2);
            }
            uint32_t bfr[2][4];
#pragma unroll
            for (int bi = 0; bi < 2; bi++) {
                int row = wn * 32 + bi * 16 + (lane & 15);
                int col = kh * 16 + ((lane >> 4) << 3);
                ldm_x4(bfr[bi], bw + row * ROWB + col * 2);
            }
#pragma unroll
            for (int mi = 0; mi < 4; mi++)
#pragma unroll
                for (int ni = 0; ni < 4; ni++) {
                    uint32_t b0 = bfr[ni >> 1][ni & 1];
                    uint32_t b1 = bfr[ni >> 1][(ni & 1) + 2];
                    mma16816(acc[mi][ni], afr[mi], b0, b1);
                }
        }
    }
#undef LOAD_CHUNK

#pragma unroll
    for (int mi = 0; mi < 4; mi++) {
#pragma unroll
        for (int half = 0; half < 2; half++) {
            int row = bm + wm * 64 + mi * 16 + (lane >> 2) + half * 8;
            if (row >= M) continue;
#pragma unroll
            for (int ni = 0; ni < 4; ni++) {
                int col = bn + wn * 32 + ni * 8 + ((lane & 3) << 1);
                float v0 = acc[mi][ni][half * 2 + 0] + bias[col + 0];
                float v1 = acc[mi][ni][half * 2 + 1] + bias[col + 1];
                if (epi == 0) {
                    float2 v = make_float2(v0, v1);
                    *(float2*)&Cout[(long long)row * Nout + col] = v;
                } else {
                    v0 = 0.5f * v0 * (1.f + erff(v0 * 0.7071067811865476f));
                    v1 = 0.5f * v1 * (1.f + erff(v1 * 0.7071067811865476f));
                    __half h0 = __float2half_rn(v0);
                    __half h1 = __float2half_rn(v1);
                    __half l0 = __float2half_rn(v0 - __half2float(h0));
                    __half l1 = __float2half_rn(v1 - __half2float(h1));
                    __half2 hp, lp;
                    hp.x = h0; hp.y = h1;
                    lp.x = l0; lp.y = l1;
                    __half* rp = C2out + (long long)row * (2LL * Nout);
                    *(__half2*)&rp[col]        = hp;
                    *(__half2*)&rp[Nout + col] = lp;
                }
            }
        }
    }
}

// ---------------- weight fold (fp32) ----------------
__global__ void __launch_bounds__(256)
combine_w_kernel(const float* __restrict__ W, const float* __restrict__ Wrel,
                 float* __restrict__ outW, int st, int r)
{
    int idx = blockIdx.x * 256 + threadIdx.x;
    if (idx >= DD * DD) return;
    int d = idx >> 8;
    int c = idx & 255;
    int h = c >> 5, f = c & 31;
    const float* wrow = W + ((long long)st * DD + d) * DD + h * DK;
    const float* wr   = Wrel + ((long long)(r * HH + h) * DK) * DK + f;
    float s = 0.f;
#pragma unroll
    for (int k = 0; k < DK; k++) s = fmaf(wrow[k], wr[k * DK], s);
    outW[idx] = s;
}

__global__ void
combine_b_kernel(const float* __restrict__ b, const float* __restrict__ Wrel,
                 float* __restrict__ outb, int st, int r)
{
    int c = blockIdx.x * blockDim.x + threadIdx.x;
    if (c >= DD) return;
    int h = c >> 5, f = c & 31;
    const float* br = b + st * DD + h * DK;
    const float* wr = Wrel + ((long long)(r * HH + h) * DK) * DK + f;
    float s = 0.f;
#pragma unroll
    for (int k = 0; k < DK; k++) s = fmaf(br[k], wr[k * DK], s);
    outb[c] = s;
}

// ---------------- split-pair conversions (fp16) ----------------
// A-side: A2[row][2K] = [hi | lo]
__global__ void __launch_bounds__(256)
pair_a_kernel(const float* __restrict__ A, __half* __restrict__ A2,
              long long total, int K)
{
    long long i = (long long)blockIdx.x * 256 + threadIdx.x;
    if (i >= total) return;
    long long row = i / K;
    int k = (int)(i - row * K);
    float v = A[i];
    __half hi = __float2half_rn(v);
    __half lo = __float2half_rn(v - __half2float(hi));
    __half* r = A2 + row * (2LL * K);
    r[k] = hi; r[K + k] = lo;
}

// B-side with transpose: W[K][Nw] -> W2[Nw][2K] = [hi | hi]
__global__ void __launch_bounds__(256)
pair_w_kernel(const float* __restrict__ W, __half* __restrict__ W2,
              int K, int Nw)
{
    int i = blockIdx.x * 256 + threadIdx.x;
    if (i >= K * Nw) return;
    int k = i / Nw, n = i - k * Nw;
    __half hi = __float2half_rn(W[i]);
    __half* r = W2 + (long long)n * (2LL * K);
    r[k] = hi; r[K + k] = hi;
}

// ---------------- merged edge phase across all relations ----------------
__device__ __constant__ int c_dt[RR]    = {0, 0, 3, 3};
__device__ __constant__ int c_pitch[RR] = {1024, 512, 512, 1024};
__device__ __constant__ int c_koff[RR]  = {0, 0, 0, 512};
__device__ __constant__ int c_voff[RR]  = {256, 256, 256, 768};

__device__ __forceinline__ const float* kv_base(int r, const float* kv1,
                                                const float* kv2, const float* kv3) {
    return (r == 1) ? kv2 : (r == 2) ? kv3 : kv1;
}

__global__ void __launch_bounds__(256)
edge_dot_all(const float* __restrict__ Q, const float* __restrict__ kv1,
             const float* __restrict__ kv2, const float* __restrict__ kv3,
             const int* __restrict__ esrc, const int* __restrict__ edst,
             const float* __restrict__ rel_bias)
{
    const int warp = threadIdx.x >> 5;
    const int lane = threadIdx.x & 31;
    const int h = lane >> 2, q = lane & 3;
    long long ge = (long long)blockIdx.x * 8 + warp;
    if (ge >= (long long)RR * EE) return;
    int r = (int)(ge / EE);
    int s = esrc[ge];
    int d = edst[ge];
    const float* kb = kv_base(r, kv1, kv2, kv3);
    const float4* qp = (const float4*)&Q[((long long)c_dt[r] * NN + d) * DD + h * DK + q * 8];
    const float4* kp = (const float4*)&kb[(long long)s * c_pitch[r] + c_koff[r] + h * DK + q * 8];
    float4 q0 = qp[0], q1 = qp[1];
    float4 k0 = kp[0], k1 = kp[1];
    float acc = q0.x * k0.x + q0.y * k0.y + q0.z * k0.z + q0.w * k0.w
              + q1.x * k1.x + q1.y * k1.y + q1.z * k1.z + q1.w * k1.w;
    acc += __shfl_xor_sync(0xffffffffu, acc, 1);
    acc += __shfl_xor_sync(0xffffffffu, acc, 2);
    if (q == 0) {
        float lg = acc * 0.17677669529663687f + rel_bias[r];
        g_logits[ge * HH + h] = lg;
        atomicMax(&g_m[((long long)r * NN + d) * HH + h], fenc(lg));
    }
}

__global__ void __launch_bounds__(256)
seg_exp_all(const int* __restrict__ edst)
{
    long long i = (long long)blockIdx.x * 256 + threadIdx.x;
    if (i >= (long long)RR * EE * HH) return;
    long long ge = i >> 3;
    int h = (int)(i & 7);
    int r = (int)(ge / EE);
    int d = edst[ge];
    long long mz = ((long long)r * NN + d) * HH + h;
    float m = fdec(g_m[mz]);
    float p = expf(g_logits[i] - m);
    g_p[i] = p;
    atomicAdd(&g_z[mz], p);
}

__global__ void __launch_bounds__(256)
seg_msg_all(const int* __restrict__ esrc, const int* __restrict__ edst,
            const float* __restrict__ kv1, const float* __restrict__ kv2,
            const float* __restrict__ kv3, float* __restrict__ agg)
{
    long long i = (long long)blockIdx.x * 256 + threadIdx.x;   // RR*EE*64
    if (i >= (long long)RR * EE * 64) return;
    long long ge = i >> 6;
    int c = (int)(i & 63) * 4;
    int h = c >> 5;
    int r = (int)(ge / EE);
    int s = esrc[ge];
    int d = edst[ge];
    float attn = g_p[ge * HH + h] / g_z[((long long)r * NN + d) * HH + h];
    const float* vb = kv_base(r, kv1, kv2, kv3);
    float4 v = *(const float4*)&vb[(long long)s * c_pitch[r] + c_voff[r] + c];
    float* dst = &agg[((long long)c_dt[r] * NN + d) * DD + c];
    asm volatile("red.global.add.v4.f32 [%0], {%1,%2,%3,%4};"
                 :: "l"(dst), "f"(attn * v.x), "f"(attn * v.y),
                    "f"(attn * v.z), "f"(attn * v.w)
                 : "memory");
}

// ---------------- layernorm(residual) [+ optional fp16-pair out] ----------------
__global__ void __launch_bounds__(256)
ln_kernel(const float* __restrict__ X, const float* __restrict__ Res,
          const float* __restrict__ G, const float* __restrict__ B,
          float* __restrict__ Out, __half* __restrict__ Out2)
{
    int row = blockIdx.x * 8 + (threadIdx.x >> 5);
    if (row >= TT * NN) return;
    int lane = threadIdx.x & 31;
    int t = row / NN;
    const float* xr = X + (long long)row * DD;
    const float* rr = Res + (long long)row * DD;
    float v[8];
    float sum = 0.f;
#pragma unroll
    for (int j = 0; j < 8; j++) {
        v[j] = xr[lane + 32 * j] + rr[lane + 32 * j];
        sum += v[j];
    }
#pragma unroll
    for (int o = 16; o > 0; o >>= 1) sum += __shfl_xor_sync(0xffffffffu, sum, o);
    float mu = sum * (1.f / 256.f);
    float var = 0.f;
#pragma unroll
    for (int j = 0; j < 8; j++) {
        float dlt = v[j] - mu;
        var = fmaf(dlt, dlt, var);
    }
#pragma unroll
    for (int o = 16; o > 0; o >>= 1) var += __shfl_xor_sync(0xffffffffu, var, o);
    float rstd = rsqrtf(var * (1.f / 256.f) + 1e-5f);
#pragma unroll
    for (int j = 0; j < 8; j++) {
        int c = lane + 32 * j;
        float y = (v[j] - mu) * rstd * G[t * DD + c] + B[t * DD + c];
        Out[(long long)row * DD + c] = y;
        if (Out2) {
            __half hi = __float2half_rn(y);
            __half lo = __float2half_rn(y - __half2float(hi));
            __half* r2 = Out2 + (long long)row * K2Q;
            r2[c] = hi; r2[DD + c] = lo;
        }
    }
}

// ---------------- launch ----------------
extern "C" void kernel_launch(void* const* d_in, const int* in_sizes, int n_in,
                              void* d_out, int out_size)
{
    const float* x       = (const float*)d_in[0];
    const int*   esrc    = (const int*)d_in[1];
    const int*   edst    = (const int*)d_in[2];
    const float* Wq      = (const float*)d_in[3];
    const float* bq      = (const float*)d_in[4];
    const float* Wk      = (const float*)d_in[5];
    const float* bk      = (const float*)d_in[6];
    const float* Wv      = (const float*)d_in[7];
    const float* bv      = (const float*)d_in[8];
    const float* W_attn  = (const float*)d_in[9];
    const float* W_msg   = (const float*)d_in[10];
    const float* relbias = (const float*)d_in[11];
    const float* ln1_g   = (const float*)d_in[12];
    const float* ln1_b   = (const float*)d_in[13];
    const float* ln2_g   = (const float*)d_in[14];
    const float* ln2_b   = (const float*)d_in[15];
    const float* ffn_w1  = (const float*)d_in[16];
    const float* ffn_b1  = (const float*)d_in[17];
    const float* ffn_w2  = (const float*)d_in[18];
    const float* ffn_b2  = (const float*)d_in[19];
    float* out = (float*)d_out;

    float *pQ, *pkv1, *pkv2, *pkv3, *pagg, *ph, *pf2, *pz;
    float *pWkr, *pWvr, *pbkv1, *pbkv2, *pbkv3;
    unsigned* pm;
    __half *px2, *ph2, *pfh, *pwq2, *pwkv1, *pwkv2, *pwkv3, *pw12, *pw22;
    cudaGetSymbolAddress((void**)&pQ, g_Q);
    cudaGetSymbolAddress((void**)&pkv1, g_kv1);
    cudaGetSymbolAddress((void**)&pkv2, g_kv2);
    cudaGetSymbolAddress((void**)&pkv3, g_kv3);
    cudaGetSymbolAddress((void**)&pagg, g_agg);
    cudaGetSymbolAddress((void**)&ph, g_h);
    cudaGetSymbolAddress((void**)&pf2, g_f2);
    cudaGetSymbolAddress((void**)&pm, g_m);
    cudaGetSymbolAddress((void**)&pz, g_z);
    cudaGetSymbolAddress((void**)&pWkr, g_Wkr);
    cudaGetSymbolAddress((void**)&pWvr, g_Wvr);
    cudaGetSymbolAddress((void**)&pbkv1, g_bkv1);
    cudaGetSymbolAddress((void**)&pbkv2, g_bkv2);
    cudaGetSymbolAddress((void**)&pbkv3, g_bkv3);
    cudaGetSymbolAddress((void**)&px2, g_x2);
    cudaGetSymbolAddress((void**)&ph2, g_h2);
    cudaGetSymbolAddress((void**)&pfh, g_fh);
    cudaGetSymbolAddress((void**)&pwq2, g_wq2);
    cudaGetSymbolAddress((void**)&pwkv1, g_wkv1);
    cudaGetSymbolAddress((void**)&pwkv2, g_wkv2);
    cudaGetSymbolAddress((void**)&pwkv3, g_wkv3);
    cudaGetSymbolAddress((void**)&pw12, g_w12);
    cudaGetSymbolAddress((void**)&pw22, g_w22);

    cudaFuncSetAttribute(mma_gemm, cudaFuncAttributeMaxDynamicSharedMemorySize, GSMEM_TOTAL);

    const long long sND = (long long)NN * DD;
    const long long sDD = (long long)DD * DD;
    const int stype[RR] = {1, 2, 3, 1};
    const int GMX = (NN + 127) / 128;   // 391
    const int CW = (DD * DD + 255) / 256;

    // launches 0-2: prereqs; launch index 3 = representative GEMM (profiled)
    {
        long long total = (long long)TT * NN * DD;
        pair_a_kernel<<<(unsigned)((total + 255) / 256), 256>>>(x, px2, total, DD);    // 0
    }
    pair_w_kernel<<<CW, 256>>>(Wq + 0 * sDD, pwq2 + 0LL * DD * K2Q, DD, DD);           // 1
    pair_w_kernel<<<CW, 256>>>(Wq + 3 * sDD, pwq2 + 3LL * DD * K2Q, DD, DD);           // 2
    {
        dim3 g(GMX, DD / 128, 1);
        mma_gemm<<<g, 256, GSMEM_TOTAL>>>(px2 + 0LL * NN * K2Q, pwq2 + 0LL * DD * K2Q, // 3
                                          bq + 0 * DD, pQ + 0 * sND, nullptr,
                                          NN, K2Q, DD, 0, 0, 0, 0, 0);
        mma_gemm<<<g, 256, GSMEM_TOTAL>>>(px2 + 3LL * NN * K2Q, pwq2 + 3LL * DD * K2Q,
                                          bq + 3 * DD, pQ + 3 * sND, nullptr,
                                          NN, K2Q, DD, 0, 0, 0, 0, 0);
    }

    // weight folds
    for (int r = 0; r < RR; r++) {
        combine_w_kernel<<<CW, 256>>>(Wk, W_attn, pWkr + (long long)r * sDD, stype[r], r);
        combine_w_kernel<<<CW, 256>>>(Wv, W_msg, pWvr + (long long)r * sDD, stype[r], r);
    }
    combine_b_kernel<<<1, DD>>>(bk, W_attn, pbkv1 + 0,   stype[0], 0);
    combine_b_kernel<<<1, DD>>>(bv, W_msg,  pbkv1 + 256, stype[0], 0);
    combine_b_kernel<<<1, DD>>>(bk, W_attn, pbkv1 + 512, stype[3], 3);
    combine_b_kernel<<<1, DD>>>(bv, W_msg,  pbkv1 + 768, stype[3], 3);
    combine_b_kernel<<<1, DD>>>(bk, W_attn, pbkv2 + 0,   stype[1], 1);
    combine_b_kernel<<<1, DD>>>(bv, W_msg,  pbkv2 + 256, stype[1], 1);
    combine_b_kernel<<<1, DD>>>(bk, W_attn, pbkv3 + 0,   stype[2], 2);
    combine_b_kernel<<<1, DD>>>(bv, W_msg,  pbkv3 + 256, stype[2], 2);
    // paired fp16 weights into concatenated buffers
    pair_w_kernel<<<CW, 256>>>(pWkr + 0LL * sDD, pwkv1 + 0LL   * K2Q, DD, DD);  // r0 k
    pair_w_kernel<<<CW, 256>>>(pWvr + 0LL * sDD, pwkv1 + 256LL * K2Q, DD, DD);  // r0 v
    pair_w_kernel<<<CW, 256>>>(pWkr + 3LL * sDD, pwkv1 + 512LL * K2Q, DD, DD);  // r3 k
    pair_w_kernel<<<CW, 256>>>(pWvr + 3LL * sDD, pwkv1 + 768LL * K2Q, DD, DD);  // r3 v
    pair_w_kernel<<<CW, 256>>>(pWkr + 1LL * sDD, pwkv2 + 0LL   * K2Q, DD, DD);  // r1 k
    pair_w_kernel<<<CW, 256>>>(pWvr + 1LL * sDD, pwkv2 + 256LL * K2Q, DD, DD);  // r1 v
    pair_w_kernel<<<CW, 256>>>(pWkr + 2LL * sDD, pwkv3 + 0LL   * K2Q, DD, DD);  // r2 k
    pair_w_kernel<<<CW, 256>>>(pWvr + 2LL * sDD, pwkv3 + 256LL * K2Q, DD, DD);  // r2 v
    for (int t = 0; t < TT; t++) {
        pair_w_kernel<<<(DD * D4 + 255) / 256, 256>>>(ffn_w1 + (long long)t * DD * D4,
                                                      pw12 + (long long)t * D4 * K2Q, DD, D4);
        pair_w_kernel<<<(D4 * DD + 255) / 256, 256>>>(ffn_w2 + (long long)t * D4 * DD,
                                                      pw22 + (long long)t * DD * K2F, D4, DD);
    }

    // batched K/V GEMMs per source type
    {
        dim3 g1(GMX, 1024 / 128, 1);
        mma_gemm<<<g1, 256, GSMEM_TOTAL>>>(px2 + 1LL * NN * K2Q, pwkv1, pbkv1, pkv1, nullptr,
                                           NN, K2Q, 1024, 0, 0, 0, 0, 0);
        dim3 g2(GMX, 512 / 128, 1);
        mma_gemm<<<g2, 256, GSMEM_TOTAL>>>(px2 + 2LL * NN * K2Q, pwkv2, pbkv2, pkv2, nullptr,
                                           NN, K2Q, 512, 0, 0, 0, 0, 0);
        mma_gemm<<<g2, 256, GSMEM_TOTAL>>>(px2 + 3LL * NN * K2Q, pwkv3, pbkv3, pkv3, nullptr,
                                           NN, K2Q, 512, 0, 0, 0, 0, 0);
    }

    // edge phase (all relations in one pass)
    cudaMemsetAsync(pagg, 0, sizeof(float) * TT * NN * DD, 0);
    cudaMemsetAsync(pm, 0, sizeof(unsigned) * RR * NN * HH, 0);
    cudaMemsetAsync(pz, 0, sizeof(float) * RR * NN * HH, 0);
    {
        long long ne = (long long)RR * EE;
        edge_dot_all<<<(unsigned)((ne + 7) / 8), 256>>>(pQ, pkv1, pkv2, pkv3, esrc, edst, relbias);
        long long nh = ne * HH;
        seg_exp_all<<<(unsigned)((nh + 255) / 256), 256>>>(edst);
        long long nm = ne * 64;
        seg_msg_all<<<(unsigned)((nm + 255) / 256), 256>>>(esrc, edst, pkv1, pkv2, pkv3, pagg);
    }

    // h = LN1(x + agg) (+ fp16 pair h2)
    ln_kernel<<<(TT * NN + 7) / 8, 256>>>(x, pagg, ln1_g, ln1_b, ph, ph2);

    // FFN1: fh = pair(gelu(h @ W1 + b1))
    {
        dim3 g(GMX, D4 / 128, TT);
        mma_gemm<<<g, 256, GSMEM_TOTAL>>>(ph2, pw12, ffn_b1, nullptr, pfh,
                                          NN, K2Q, D4,
                                          (long long)NN * K2Q, (long long)D4 * K2Q,
                                          D4, (long long)NN * D4, 1);
    }
    // FFN2: f2 = fh @ W2 + b2
    {
        dim3 g(GMX, DD / 128, TT);
        mma_gemm<<<g, 256, GSMEM_TOTAL>>>(pfh, pw22, ffn_b2, pf2, nullptr,
                                          NN, K2F, DD,
                                          (long long)NN * K2F, (long long)DD * K2F,
                                          DD, sND, 0);
    }

    // out = LN2(h + f2)
    ln_kernel<<<(TT * NN + 7) / 8, 256>>>(ph, pf2, ln2_g, ln2_b, out, nullptr);

    (void)in_sizes; (void)n_in; (void)out_size;
}